// round 2
// baseline (speedup 1.0000x reference)
#include <cuda_runtime.h>

// Problem constants: x (8, 512, 4096) fp32; W* (512,512); b* (512,)
#define BB 8
#define CC 512
#define TT 4096
#define SCALE_F 0.125f   // 64^-0.5

// Scratch (allocation-free rule: __device__ globals)
__device__ float g_q[(size_t)BB * CC * TT];     // 64 MB
__device__ float g_k[(size_t)BB * CC * TT];     // 64 MB
__device__ float g_v[(size_t)BB * CC * TT];     // 64 MB
__device__ float g_dots[(size_t)BB * CC * CC];  // 8 MB

#define BM 128
#define BN 128
#define BK 8
#define PAD 4

// ---------------------------------------------------------------------------
// NN GEMM: C[m,n] = sum_k A[m,k] * B[k,n]  (+ optional bias[m])
// A: M x K row-major (lda = K), B: K x N row-major (ldb = N), C: M x N (ldc = N)
// Batched via blockIdx.z with element strides. M%128==0, N%128==0, K%8==0.
// ---------------------------------------------------------------------------
template <bool HAS_BIAS>
__global__ __launch_bounds__(256, 2) void gemm_nn_kernel(
    const float* __restrict__ A, size_t strideA,
    const float* __restrict__ Bm, size_t strideB,
    float* __restrict__ Cm, size_t strideC,
    const float* __restrict__ bias,
    int M, int N, int K)
{
    const float* Ab = A + (size_t)blockIdx.z * strideA;
    const float* Bb = Bm + (size_t)blockIdx.z * strideB;
    float*       Cb = Cm + (size_t)blockIdx.z * strideC;

    __shared__ float As[BK][BM + PAD];
    __shared__ float Bs[BK][BN + PAD];

    const int tid = threadIdx.x;            // 0..255
    const int m0 = blockIdx.y * BM;
    const int n0 = blockIdx.x * BN;

    const int aRow = tid >> 1;              // 0..127
    const int aSeg = (tid & 1) * 4;         // 0 or 4
    const int bRow = tid >> 5;              // 0..7
    const int bCol = (tid & 31) * 4;        // 0..124

    const int tx = tid & 15;                // col group
    const int ty = tid >> 4;                // row group

    float acc[8][8];
#pragma unroll
    for (int i = 0; i < 8; i++)
#pragma unroll
        for (int j = 0; j < 8; j++) acc[i][j] = 0.0f;

    for (int k0 = 0; k0 < K; k0 += BK) {
        // A tile load (transpose into As[k][m])
        float4 av = *(const float4*)(Ab + (size_t)(m0 + aRow) * K + k0 + aSeg);
        As[aSeg + 0][aRow] = av.x;
        As[aSeg + 1][aRow] = av.y;
        As[aSeg + 2][aRow] = av.z;
        As[aSeg + 3][aRow] = av.w;
        // B tile load (direct)
        float4 bv = *(const float4*)(Bb + (size_t)(k0 + bRow) * N + n0 + bCol);
        *(float4*)(&Bs[bRow][bCol]) = bv;
        __syncthreads();

#pragma unroll
        for (int kk = 0; kk < BK; kk++) {
            float a[8], b[8];
#pragma unroll
            for (int i = 0; i < 8; i++) a[i] = As[kk][ty * 8 + i];
#pragma unroll
            for (int j = 0; j < 8; j++) b[j] = Bs[kk][tx * 8 + j];
#pragma unroll
            for (int i = 0; i < 8; i++)
#pragma unroll
                for (int j = 0; j < 8; j++)
                    acc[i][j] = fmaf(a[i], b[j], acc[i][j]);
        }
        __syncthreads();
    }

#pragma unroll
    for (int i = 0; i < 8; i++) {
        const int m = m0 + ty * 8 + i;
        const float bb = HAS_BIAS ? bias[m] : 0.0f;
        float* crow = Cb + (size_t)m * N + n0 + tx * 8;
        float4 o0 = make_float4(acc[i][0] + bb, acc[i][1] + bb,
                                acc[i][2] + bb, acc[i][3] + bb);
        float4 o1 = make_float4(acc[i][4] + bb, acc[i][5] + bb,
                                acc[i][6] + bb, acc[i][7] + bb);
        *(float4*)(crow + 0) = o0;
        *(float4*)(crow + 4) = o1;
    }
}

// ---------------------------------------------------------------------------
// NT GEMM: C[m,n] = scale * sum_k A[m,k] * B[n,k]
// A: M x K row-major (lda = K), B: N x K row-major (ldb = K), C: M x N (ldc = N)
// ---------------------------------------------------------------------------
__global__ __launch_bounds__(256, 2) void gemm_nt_kernel(
    const float* __restrict__ A, size_t strideA,
    const float* __restrict__ Bm, size_t strideB,
    float* __restrict__ Cm, size_t strideC,
    float scale, int M, int N, int K)
{
    const float* Ab = A + (size_t)blockIdx.z * strideA;
    const float* Bb = Bm + (size_t)blockIdx.z * strideB;
    float*       Cb = Cm + (size_t)blockIdx.z * strideC;

    __shared__ float As[BK][BM + PAD];
    __shared__ float Bs[BK][BN + PAD];

    const int tid = threadIdx.x;
    const int m0 = blockIdx.y * BM;
    const int n0 = blockIdx.x * BN;

    const int row = tid >> 1;               // 0..127
    const int seg = (tid & 1) * 4;          // 0 or 4
    const int tx = tid & 15;
    const int ty = tid >> 4;

    float acc[8][8];
#pragma unroll
    for (int i = 0; i < 8; i++)
#pragma unroll
        for (int j = 0; j < 8; j++) acc[i][j] = 0.0f;

    for (int k0 = 0; k0 < K; k0 += BK) {
        float4 av = *(const float4*)(Ab + (size_t)(m0 + row) * K + k0 + seg);
        float4 bv = *(const float4*)(Bb + (size_t)(n0 + row) * K + k0 + seg);
        As[seg + 0][row] = av.x; As[seg + 1][row] = av.y;
        As[seg + 2][row] = av.z; As[seg + 3][row] = av.w;
        Bs[seg + 0][row] = bv.x; Bs[seg + 1][row] = bv.y;
        Bs[seg + 2][row] = bv.z; Bs[seg + 3][row] = bv.w;
        __syncthreads();

#pragma unroll
        for (int kk = 0; kk < BK; kk++) {
            float a[8], b[8];
#pragma unroll
            for (int i = 0; i < 8; i++) a[i] = As[kk][ty * 8 + i];
#pragma unroll
            for (int j = 0; j < 8; j++) b[j] = Bs[kk][tx * 8 + j];
#pragma unroll
            for (int i = 0; i < 8; i++)
#pragma unroll
                for (int j = 0; j < 8; j++)
                    acc[i][j] = fmaf(a[i], b[j], acc[i][j]);
        }
        __syncthreads();
    }

#pragma unroll
    for (int i = 0; i < 8; i++) {
        const int m = m0 + ty * 8 + i;
        float* crow = Cb + (size_t)m * N + n0 + tx * 8;
        float4 o0 = make_float4(acc[i][0] * scale, acc[i][1] * scale,
                                acc[i][2] * scale, acc[i][3] * scale);
        float4 o1 = make_float4(acc[i][4] * scale, acc[i][5] * scale,
                                acc[i][6] * scale, acc[i][7] * scale);
        *(float4*)(crow + 0) = o0;
        *(float4*)(crow + 4) = o1;
    }
}

// ---------------------------------------------------------------------------
// Row softmax over 512-element rows; one warp per row (in place).
// ---------------------------------------------------------------------------
__global__ void softmax_kernel(float* __restrict__ d, int rows)
{
    const int gw = (blockIdx.x * blockDim.x + threadIdx.x) >> 5;
    if (gw >= rows) return;
    const int lane = threadIdx.x & 31;
    float4* r = (float4*)(d + (size_t)gw * CC);

    float4 v[4];
    float mx = -1e30f;
#pragma unroll
    for (int i = 0; i < 4; i++) {
        v[i] = r[lane + 32 * i];
        mx = fmaxf(mx, fmaxf(fmaxf(v[i].x, v[i].y), fmaxf(v[i].z, v[i].w)));
    }
#pragma unroll
    for (int o = 16; o > 0; o >>= 1)
        mx = fmaxf(mx, __shfl_xor_sync(0xffffffffu, mx, o));

    float s = 0.0f;
#pragma unroll
    for (int i = 0; i < 4; i++) {
        v[i].x = expf(v[i].x - mx);
        v[i].y = expf(v[i].y - mx);
        v[i].z = expf(v[i].z - mx);
        v[i].w = expf(v[i].w - mx);
        s += v[i].x + v[i].y + v[i].z + v[i].w;
    }
#pragma unroll
    for (int o = 16; o > 0; o >>= 1)
        s += __shfl_xor_sync(0xffffffffu, s, o);

    const float inv = 1.0f / s;
#pragma unroll
    for (int i = 0; i < 4; i++) {
        v[i].x *= inv; v[i].y *= inv; v[i].z *= inv; v[i].w *= inv;
        r[lane + 32 * i] = v[i];
    }
}

// ---------------------------------------------------------------------------
// Launch: q,k,v proj (3x NN GEMM) -> dots (NT) -> softmax -> out (NN)
// Inputs (metadata order): x, Wq, bq, Wk, bk, Wv, bv
// ---------------------------------------------------------------------------
extern "C" void kernel_launch(void* const* d_in, const int* in_sizes, int n_in,
                              void* d_out, int out_size)
{
    (void)in_sizes; (void)n_in; (void)out_size;
    const float* x  = (const float*)d_in[0];
    const float* Wq = (const float*)d_in[1];
    const float* bq = (const float*)d_in[2];
    const float* Wk = (const float*)d_in[3];
    const float* bk = (const float*)d_in[4];
    const float* Wv = (const float*)d_in[5];
    const float* bv = (const float*)d_in[6];
    float* out = (float*)d_out;

    float *q, *k, *v, *dots;
    cudaGetSymbolAddress((void**)&q, g_q);
    cudaGetSymbolAddress((void**)&k, g_k);
    cudaGetSymbolAddress((void**)&v, g_v);
    cudaGetSymbolAddress((void**)&dots, g_dots);

    const size_t CT = (size_t)CC * TT;   // per-batch q/k/v/x/out stride
    const size_t CCs = (size_t)CC * CC;  // per-batch dots stride

    dim3 blk(256);

    // QKV projections: M=512 (o), N=4096 (t), K=512 (c); A=W shared across batch
    dim3 gProj(TT / BN, CC / BM, BB);    // (32, 4, 8)
    gemm_nn_kernel<true><<<gProj, blk>>>(Wq, 0, x, CT, q, CT, bq, CC, TT, CC);
    gemm_nn_kernel<true><<<gProj, blk>>>(Wk, 0, x, CT, k, CT, bk, CC, TT, CC);
    gemm_nn_kernel<true><<<gProj, blk>>>(Wv, 0, x, CT, v, CT, bv, CC, TT, CC);

    // dots = SCALE * q @ k^T per batch: M=512, N=512, K=4096
    dim3 gDots(CC / BN, CC / BM, BB);    // (4, 4, 8)
    gemm_nt_kernel<<<gDots, blk>>>(q, CT, k, CT, dots, CCs, SCALE_F, CC, CC, TT);

    // softmax over last axis: 8*512 rows of 512
    {
        int rows = BB * CC;              // 4096
        int threads = 128;               // 4 warps -> 4 rows per block
        int grid = rows / 4;             // 1024
        softmax_kernel<<<grid, threads>>>(dots, rows);
    }

    // out = attn @ v per batch: M=512 (c), N=4096 (t), K=512 (d)
    dim3 gOut(TT / BN, CC / BM, BB);     // (32, 4, 8)
    gemm_nn_kernel<false><<<gOut, blk>>>(dots, CCs, v, CT, out, CT, nullptr, CC, TT, CC);
}

// round 4
// speedup vs baseline: 2.9757x; 2.9757x over previous
#include <cuda_runtime.h>
#include <cuda_bf16.h>

typedef __nv_bfloat16 bf16;
typedef unsigned int u32;

#define BB 8
#define CC 512
#define TT 4096
#define SCALE_F 0.125f
#define NELEM ((size_t)BB * CC * TT)
#define CCSQ ((size_t)CC * CC)
#define KSPL_DOTS 4

__device__ bf16 g_xT_h[NELEM];
__device__ bf16 g_xT_l[NELEM];
__device__ bf16 g_w_h[3][CC * CC];
__device__ bf16 g_w_l[3][CC * CC];
__device__ bf16 g_q_h[NELEM];
__device__ bf16 g_q_l[NELEM];
__device__ bf16 g_k_h[NELEM];
__device__ bf16 g_k_l[NELEM];
__device__ bf16 g_vT_h[NELEM];
__device__ bf16 g_vT_l[NELEM];
__device__ float g_dots[(size_t)KSPL_DOTS * BB * CC * CC];  // 32 MB partials
__device__ bf16 g_a_h[(size_t)BB * CC * CC];
__device__ bf16 g_a_l[(size_t)BB * CC * CC];

__device__ __forceinline__ u32 smem_u32(const void* p) {
    u32 a;
    asm("{ .reg .u64 t; cvta.to.shared.u64 t, %1; cvt.u32.u64 %0, t; }" : "=r"(a) : "l"(p));
    return a;
}
__device__ __forceinline__ void split2(float a, float b, u32& h, u32& l) {
    bf16 h0 = __float2bfloat16(a), h1 = __float2bfloat16(b);
    bf16 l0 = __float2bfloat16(a - __bfloat162float(h0));
    bf16 l1 = __float2bfloat16(b - __bfloat162float(h1));
    __nv_bfloat162 hh(h0, h1), ll(l0, l1);
    h = *(u32*)&hh;
    l = *(u32*)&ll;
}
__device__ __forceinline__ void ldsm4(u32& r0, u32& r1, u32& r2, u32& r3, u32 addr) {
    asm volatile("ldmatrix.sync.aligned.m8n8.x4.shared.b16 {%0,%1,%2,%3}, [%4];"
                 : "=r"(r0), "=r"(r1), "=r"(r2), "=r"(r3) : "r"(addr));
}
__device__ __forceinline__ void mma16816(float* d, const u32* a, u32 b0, u32 b1) {
    asm volatile(
        "mma.sync.aligned.m16n8k16.row.col.f32.bf16.bf16.f32 "
        "{%0,%1,%2,%3}, {%4,%5,%6,%7}, {%8,%9}, {%0,%1,%2,%3};"
        : "+f"(d[0]), "+f"(d[1]), "+f"(d[2]), "+f"(d[3])
        : "r"(a[0]), "r"(a[1]), "r"(a[2]), "r"(a[3]), "r"(b0), "r"(b1));
}

// cp.async 128 rows x 64 bf16 (128B rows) with SW128 swizzle; 256 threads.
__device__ __forceinline__ void cp_tile(u32 sdst, const bf16* g, int ld, int tid) {
    const int seg = tid & 7;
    const int r0 = tid >> 3;
    const char* gc = (const char*)g + seg * 16;
#pragma unroll
    for (int p = 0; p < 4; p++) {
        int row = p * 32 + r0;
        u32 dst = sdst + row * 128 + ((seg ^ (row & 7)) << 4);
        const void* src = gc + (size_t)row * ld * sizeof(bf16);
        asm volatile("cp.async.cg.shared.global [%0], [%1], 16;" :: "r"(dst), "l"(src) : "memory");
    }
}

// D[m,n] = scale*sum_k A[m,k]*B[n,k] (+bias); split-bf16, 3 segments in reg accum.
// BM=BN=128, BK=64. 256 threads, 8 warps (4M x 2N), warp tile 32x64.
template <bool BIASCOL, bool SPLIT, int KSPL>
__global__ __launch_bounds__(256) void gemm_mma(
    const bf16* __restrict__ Ah, const bf16* __restrict__ Al, size_t sA, int lda,
    const bf16* __restrict__ Bh, const bf16* __restrict__ Bl, size_t sB, int ldb,
    float* __restrict__ C, bf16* __restrict__ Ch, bf16* __restrict__ Cl,
    size_t sC, int ldc, const float* __restrict__ bias, float scale, int K)
{
    extern __shared__ char dyn[];
    char* dg = (char*)(((size_t)dyn + 1023) & ~(size_t)1023);
    const u32 base = smem_u32(dg);       // 3 stages x (A 16KB + B 16KB)

    const int tid = threadIdx.x, wid = tid >> 5, lane = tid & 31;
    const int z = blockIdx.z;
    const int batch = z / KSPL, ksl = z - batch * KSPL;
    const int m0 = blockIdx.y * 128, n0 = blockIdx.x * 128;
    const int wm = wid & 3, wn = wid >> 2;

    const bf16* Azh = Ah + (size_t)batch * sA + (size_t)ksl * K + (size_t)m0 * lda;
    const bf16* Azl = Al + (size_t)batch * sA + (size_t)ksl * K + (size_t)m0 * lda;
    const bf16* Bzh = Bh + (size_t)batch * sB + (size_t)ksl * K + (size_t)n0 * ldb;
    const bf16* Bzl = Bl + (size_t)batch * sB + (size_t)ksl * K + (size_t)n0 * ldb;
    const bf16* Asrc[3] = {Azh, Azl, Azh};
    const bf16* Bsrc[3] = {Bzh, Bzh, Bzl};

    const int NCH = K >> 6;          // chunks per segment
    const int total = 3 * NCH;

    float acc[2][8][4];
#pragma unroll
    for (int i = 0; i < 2; i++)
#pragma unroll
        for (int j = 0; j < 8; j++)
#pragma unroll
            for (int t = 0; t < 4; t++) acc[i][j][t] = 0.0f;

    // prologue: fill 3 stages
#pragma unroll
    for (int c = 0; c < 3; c++) {
        int s = c / NCH, kc = c - s * NCH;   // NCH>=4 always so s=0
        u32 sb = base + c * 32768;
        cp_tile(sb, Asrc[s] + kc * 64, lda, tid);
        cp_tile(sb + 16384, Bsrc[s] + kc * 64, ldb, tid);
        asm volatile("cp.async.commit_group;" ::: "memory");
    }

    for (int c = 0; c < total; c++) {
        asm volatile("cp.async.wait_group 2;" ::: "memory");
        __syncthreads();

        const int st = c % 3;
        const u32 sAa = base + st * 32768;
        const u32 sBb = sAa + 16384;

#pragma unroll
        for (int ks = 0; ks < 4; ks++) {
            u32 a[2][4];
#pragma unroll
            for (int mi = 0; mi < 2; mi++) {
                int row = wm * 32 + mi * 16 + (lane & 15);
                u32 addr = sAa + row * 128 + ((((ks << 1) | (lane >> 4)) ^ (row & 7)) << 4);
                ldsm4(a[mi][0], a[mi][1], a[mi][2], a[mi][3], addr);
            }
            u32 b[4][4];
#pragma unroll
            for (int ni = 0; ni < 4; ni++) {
                int row = wn * 64 + ni * 16 + (lane & 15);
                u32 addr = sBb + row * 128 + ((((ks << 1) | (lane >> 4)) ^ (row & 7)) << 4);
                ldsm4(b[ni][0], b[ni][1], b[ni][2], b[ni][3], addr);
            }
#pragma unroll
            for (int mi = 0; mi < 2; mi++)
#pragma unroll
                for (int ni = 0; ni < 4; ni++) {
                    mma16816(acc[mi][2 * ni + 0], a[mi], b[ni][0], b[ni][2]);
                    mma16816(acc[mi][2 * ni + 1], a[mi], b[ni][1], b[ni][3]);
                }
        }
        __syncthreads();
        int nc = c + 3;
        if (nc < total) {
            int s = nc / NCH, kc = nc - s * NCH;
            u32 sb = base + st * 32768;
            cp_tile(sb, Asrc[s] + kc * 64, lda, tid);
            cp_tile(sb + 16384, Bsrc[s] + kc * 64, ldb, tid);
            asm volatile("cp.async.commit_group;" ::: "memory");
        } else {
            asm volatile("cp.async.commit_group;" ::: "memory");  // keep group count in sync
        }
    }

    // epilogue
    const int mwarp = m0 + wm * 32;
    const int nwarp = n0 + wn * 64;
#pragma unroll
    for (int mi = 0; mi < 2; mi++) {
        const int r0 = mwarp + mi * 16 + (lane >> 2);
        float br0 = 0.f, br1 = 0.f;
        if (!BIASCOL && bias) { br0 = bias[r0]; br1 = bias[r0 + 8]; }
#pragma unroll
        for (int nj = 0; nj < 8; nj++) {
            const int col = nwarp + nj * 8 + (lane & 3) * 2;
            float bc0 = 0.f, bc1 = 0.f;
            if (BIASCOL && bias) { bc0 = bias[col]; bc1 = bias[col + 1]; }
            const float* d = acc[mi][nj];
            float v00 = d[0] * scale + (BIASCOL ? bc0 : br0);
            float v01 = d[1] * scale + (BIASCOL ? bc1 : br0);
            float v10 = d[2] * scale + (BIASCOL ? bc0 : br1);
            float v11 = d[3] * scale + (BIASCOL ? bc1 : br1);
            const size_t i0 = (size_t)z * sC + (size_t)r0 * ldc + col;
            const size_t i1 = i0 + (size_t)8 * ldc;
            if (SPLIT) {
                u32 h, l;
                split2(v00, v01, h, l);
                *(u32*)(Ch + i0) = h; *(u32*)(Cl + i0) = l;
                split2(v10, v11, h, l);
                *(u32*)(Ch + i1) = h; *(u32*)(Cl + i1) = l;
            } else {
                *(float2*)(C + i0) = make_float2(v00, v01);
                *(float2*)(C + i1) = make_float2(v10, v11);
            }
        }
    }
}

__global__ void split_kernel(const float* __restrict__ in, bf16* __restrict__ oh,
                             bf16* __restrict__ ol, size_t n)
{
    size_t i = ((size_t)blockIdx.x * blockDim.x + threadIdx.x) * 4;
    if (i >= n) return;
    float4 v = *(const float4*)(in + i);
    uint2 uh, ul;
    split2(v.x, v.y, uh.x, ul.x);
    split2(v.z, v.w, uh.y, ul.y);
    *(uint2*)(oh + i) = uh;
    *(uint2*)(ol + i) = ul;
}

__global__ void tsplit_kernel(const float* __restrict__ in, bf16* __restrict__ oh,
                              bf16* __restrict__ ol)
{
    __shared__ float t[32][33];
    const int t0 = blockIdx.x * 32, c0 = blockIdx.y * 32, z = blockIdx.z;
    const int tx = threadIdx.x, ty = threadIdx.y;
    const float* inz = in + (size_t)z * CC * TT;
#pragma unroll
    for (int p = 0; p < 4; p++)
        t[ty + p * 8][tx] = inz[(size_t)(c0 + ty + p * 8) * TT + t0 + tx];
    __syncthreads();
    const size_t ob = (size_t)z * TT * CC;
#pragma unroll
    for (int p = 0; p < 4; p++) {
        float v = t[tx][ty + p * 8];
        bf16 h = __float2bfloat16(v);
        bf16 l = __float2bfloat16(v - __bfloat162float(h));
        size_t o = ob + (size_t)(t0 + ty + p * 8) * CC + c0 + tx;
        oh[o] = h;
        ol[o] = l;
    }
}

// sum 4 split-K partials, softmax over 512, bf16 hi/lo split out
__global__ void softmax4_split_kernel(const float* __restrict__ d, bf16* __restrict__ ah,
                                      bf16* __restrict__ al)
{
    const int gw = (blockIdx.x * blockDim.x + threadIdx.x) >> 5;   // row: b*512 + c
    const int lane = threadIdx.x & 31;
    const int b = gw >> 9, c = gw & 511;
    const float4* r0 = (const float4*)(d + ((size_t)(b * KSPL_DOTS + 0) << 18) + (size_t)c * CC);
    const float4* r1 = (const float4*)(d + ((size_t)(b * KSPL_DOTS + 1) << 18) + (size_t)c * CC);
    const float4* r2 = (const float4*)(d + ((size_t)(b * KSPL_DOTS + 2) << 18) + (size_t)c * CC);
    const float4* r3 = (const float4*)(d + ((size_t)(b * KSPL_DOTS + 3) << 18) + (size_t)c * CC);
    float4 v[4];
    float mx = -1e30f;
#pragma unroll
    for (int i = 0; i < 4; i++) {
        const int idx = lane + 32 * i;
        float4 a0 = r0[idx], a1 = r1[idx], a2 = r2[idx], a3 = r3[idx];
        v[i].x = a0.x + a1.x + a2.x + a3.x;
        v[i].y = a0.y + a1.y + a2.y + a3.y;
        v[i].z = a0.z + a1.z + a2.z + a3.z;
        v[i].w = a0.w + a1.w + a2.w + a3.w;
        mx = fmaxf(mx, fmaxf(fmaxf(v[i].x, v[i].y), fmaxf(v[i].z, v[i].w)));
    }
#pragma unroll
    for (int o = 16; o > 0; o >>= 1) mx = fmaxf(mx, __shfl_xor_sync(~0u, mx, o));
    float s = 0.f;
#pragma unroll
    for (int i = 0; i < 4; i++) {
        v[i].x = expf(v[i].x - mx); v[i].y = expf(v[i].y - mx);
        v[i].z = expf(v[i].z - mx); v[i].w = expf(v[i].w - mx);
        s += v[i].x + v[i].y + v[i].z + v[i].w;
    }
#pragma unroll
    for (int o = 16; o > 0; o >>= 1) s += __shfl_xor_sync(~0u, s, o);
    const float inv = 1.0f / s;
#pragma unroll
    for (int i = 0; i < 4; i++) {
        uint2 uh, ul;
        split2(v[i].x * inv, v[i].y * inv, uh.x, ul.x);
        split2(v[i].z * inv, v[i].w * inv, uh.y, ul.y);
        size_t o = (size_t)gw * CC + 4 * (lane + 32 * i);
        *(uint2*)(ah + o) = uh;
        *(uint2*)(al + o) = ul;
    }
}

extern "C" void kernel_launch(void* const* d_in, const int* in_sizes, int n_in,
                              void* d_out, int out_size)
{
    (void)in_sizes; (void)n_in; (void)out_size;
    const float* x = (const float*)d_in[0];
    const float* W[3] = {(const float*)d_in[1], (const float*)d_in[3], (const float*)d_in[5]};
    const float* bq = (const float*)d_in[2];
    const float* bk = (const float*)d_in[4];
    const float* bv = (const float*)d_in[6];
    float* out = (float*)d_out;

    bf16 *xTh, *xTl, *wh, *wl, *qh, *ql, *kh, *kl, *vTh, *vTl, *aH, *aL;
    float* dots;
    cudaGetSymbolAddress((void**)&xTh, g_xT_h);
    cudaGetSymbolAddress((void**)&xTl, g_xT_l);
    cudaGetSymbolAddress((void**)&wh, g_w_h);
    cudaGetSymbolAddress((void**)&wl, g_w_l);
    cudaGetSymbolAddress((void**)&qh, g_q_h);
    cudaGetSymbolAddress((void**)&ql, g_q_l);
    cudaGetSymbolAddress((void**)&kh, g_k_h);
    cudaGetSymbolAddress((void**)&kl, g_k_l);
    cudaGetSymbolAddress((void**)&vTh, g_vT_h);
    cudaGetSymbolAddress((void**)&vTl, g_vT_l);
    cudaGetSymbolAddress((void**)&dots, g_dots);
    cudaGetSymbolAddress((void**)&aH, g_a_h);
    cudaGetSymbolAddress((void**)&aL, g_a_l);

    const size_t CT = (size_t)CC * TT;
    const int SMEMSZ = 3 * 32768 + 1024;

    cudaFuncSetAttribute(gemm_mma<false, true, 1>, cudaFuncAttributeMaxDynamicSharedMemorySize, SMEMSZ);
    cudaFuncSetAttribute(gemm_mma<true, true, 1>, cudaFuncAttributeMaxDynamicSharedMemorySize, SMEMSZ);
    cudaFuncSetAttribute(gemm_mma<false, false, KSPL_DOTS>, cudaFuncAttributeMaxDynamicSharedMemorySize, SMEMSZ);
    cudaFuncSetAttribute(gemm_mma<false, false, 1>, cudaFuncAttributeMaxDynamicSharedMemorySize, SMEMSZ);

    for (int i = 0; i < 3; i++)
        split_kernel<<<CC * CC / 1024, 256>>>(W[i], wh + (size_t)i * CCSQ, wl + (size_t)i * CCSQ, CCSQ);
    tsplit_kernel<<<dim3(TT / 32, CC / 32, BB), dim3(32, 8)>>>(x, xTh, xTl);

    // Q/K proj: D[o][t], M=512, N=4096, K=512
    dim3 gProj(TT / 128, CC / 128, BB);
    gemm_mma<false, true, 1><<<gProj, 256, SMEMSZ>>>(
        wh, wl, 0, CC, xTh, xTl, CT, CC, nullptr, qh, ql, CT, TT, bq, 1.0f, CC);
    gemm_mma<false, true, 1><<<gProj, 256, SMEMSZ>>>(
        wh + CCSQ, wl + CCSQ, 0, CC, xTh, xTl, CT, CC, nullptr, kh, kl, CT, TT, bk, 1.0f, CC);
    // V proj transposed: vT[t][d], M=4096, N=512, K=512, col bias
    dim3 gV(CC / 128, TT / 128, BB);
    gemm_mma<true, true, 1><<<gV, 256, SMEMSZ>>>(
        xTh, xTl, CT, CC, wh + 2 * CCSQ, wl + 2 * CCSQ, 0, CC, nullptr, vTh, vTl, CT, CC, bv, 1.0f, CC);
    // dots split-K x4: M=N=512, K=1024 per slice
    dim3 gD(CC / 128, CC / 128, BB * KSPL_DOTS);
    gemm_mma<false, false, KSPL_DOTS><<<gD, 256, SMEMSZ>>>(
        qh, ql, CT, TT, kh, kl, CT, TT, dots, nullptr, nullptr, CCSQ, CC, nullptr, SCALE_F, TT / KSPL_DOTS);
    // softmax (sums partials) + split
    softmax4_split_kernel<<<BB * CC / 4, 128>>>(dots, aH, aL);
    // out: M=512, N=4096, K=512
    gemm_mma<false, false, 1><<<gProj, 256, SMEMSZ>>>(
        aH, aL, CCSQ, CC, vTh, vTl, CT, CC, out, nullptr, nullptr, CT, TT, nullptr, 1.0f, CC);
}

// round 5
// speedup vs baseline: 5.4143x; 1.8195x over previous
#include <cuda_runtime.h>
#include <cuda_fp16.h>

typedef unsigned int u32;

#define BB 8
#define CC 512
#define TT 4096
#define SCALE_F 0.125f
#define NELEM ((size_t)BB * CC * TT)
#define CCSQ ((size_t)CC * CC)
#define KSPL_G 4

// ---------------- scratch ----------------
__device__ half g_x_h[NELEM];
__device__ half g_x_l[NELEM];
__device__ half g_xT_h[NELEM];
__device__ half g_xT_l[NELEM];
__device__ half g_wq_h[CCSQ];
__device__ half g_wq_l[CCSQ];
__device__ half g_wk_h[CCSQ];
__device__ half g_wk_l[CCSQ];
__device__ half g_wvT_h[CCSQ];
__device__ half g_wvT_l[CCSQ];
__device__ float g_part[(size_t)KSPL_G * BB * CCSQ];
__device__ half g_G_h[(size_t)BB * CCSQ];
__device__ half g_G_l[(size_t)BB * CCSQ];
__device__ half g_t2_h[(size_t)BB * CCSQ];
__device__ half g_t2_l[(size_t)BB * CCSQ];
__device__ float g_dots[(size_t)BB * CCSQ];
__device__ half g_a_h[(size_t)BB * CCSQ];
__device__ half g_a_l[(size_t)BB * CCSQ];
__device__ half g_P_h[(size_t)BB * CCSQ];
__device__ half g_P_l[(size_t)BB * CCSQ];
__device__ float g_sx[BB * CC];
__device__ float g_w1[BB * CC];
__device__ float g_w2[BB * CC];
__device__ float g_pb[BB * CC];

// ---------------- helpers ----------------
__device__ __forceinline__ u32 smem_u32(const void* p) {
    u32 a;
    asm("{ .reg .u64 t; cvta.to.shared.u64 t, %1; cvt.u32.u64 %0, t; }" : "=r"(a) : "l"(p));
    return a;
}
__device__ __forceinline__ void split2h(float a, float b, u32& h, u32& l) {
    __half h0 = __float2half_rn(a), h1 = __float2half_rn(b);
    __half l0 = __float2half_rn(a - __half2float(h0));
    __half l1 = __float2half_rn(b - __half2float(h1));
    __half2 hh = __halves2half2(h0, h1), ll = __halves2half2(l0, l1);
    h = *(u32*)&hh;
    l = *(u32*)&ll;
}
__device__ __forceinline__ void ldsm4(u32& r0, u32& r1, u32& r2, u32& r3, u32 addr) {
    asm volatile("ldmatrix.sync.aligned.m8n8.x4.shared.b16 {%0,%1,%2,%3}, [%4];"
                 : "=r"(r0), "=r"(r1), "=r"(r2), "=r"(r3) : "r"(addr));
}
__device__ __forceinline__ void mma16816(float* d, const u32* a, u32 b0, u32 b1) {
    asm volatile(
        "mma.sync.aligned.m16n8k16.row.col.f32.f16.f16.f32 "
        "{%0,%1,%2,%3}, {%4,%5,%6,%7}, {%8,%9}, {%0,%1,%2,%3};"
        : "+f"(d[0]), "+f"(d[1]), "+f"(d[2]), "+f"(d[3])
        : "r"(a[0]), "r"(a[1]), "r"(a[2]), "r"(a[3]), "r"(b0), "r"(b1));
}
// cp.async 128 rows x 64 half (128B rows) with SW128 swizzle; 256 threads.
__device__ __forceinline__ void cp_tile(u32 sdst, const half* g, int ld, int tid) {
    const int seg = tid & 7;
    const int r0 = tid >> 3;
    const char* gc = (const char*)g + seg * 16;
#pragma unroll
    for (int p = 0; p < 4; p++) {
        int row = p * 32 + r0;
        u32 dst = sdst + row * 128 + ((seg ^ (row & 7)) << 4);
        const void* src = gc + (size_t)row * ld * sizeof(half);
        asm volatile("cp.async.cg.shared.global [%0], [%1], 16;" :: "r"(dst), "l"(src) : "memory");
    }
}

// ---------------------------------------------------------------------------
// NT GEMM, fp16 2-term split, 3 products (AhBh + AlBh + AhBl) with fragment
// reuse. BM=BN=128, BK=64. 8 warps (4M x 2N). 2-stage pipeline, combined
// chunk loads (Ah,Al,Bh,Bl per stage).
// ---------------------------------------------------------------------------
template <bool BIASROW, bool SPLIT, int KSPL>
__global__ __launch_bounds__(256) void gemm_mma(
    const half* __restrict__ Ah, const half* __restrict__ Al, size_t sA, int lda,
    const half* __restrict__ Bh, const half* __restrict__ Bl, size_t sB, int ldb,
    float* __restrict__ C, half* __restrict__ Ch, half* __restrict__ Cl,
    size_t sC, int ldc, const float* __restrict__ bias, int biasZ,
    float scale, int K)
{
    extern __shared__ char dyn[];
    char* dg = (char*)(((size_t)dyn + 1023) & ~(size_t)1023);
    const u32 base = smem_u32(dg);    // 2 stages x 64KB (Ah,Al,Bh,Bl 16KB each)

    const int tid = threadIdx.x, wid = tid >> 5, lane = tid & 31;
    const int z = blockIdx.z;
    const int batch = z / KSPL, ksl = z - batch * KSPL;
    const int m0 = blockIdx.y * 128, n0 = blockIdx.x * 128;
    const int wm = wid & 3, wn = wid >> 2;

    const half* pAh = Ah + (size_t)batch * sA + (size_t)ksl * K + (size_t)m0 * lda;
    const half* pAl = Al + (size_t)batch * sA + (size_t)ksl * K + (size_t)m0 * lda;
    const half* pBh = Bh + (size_t)batch * sB + (size_t)ksl * K + (size_t)n0 * ldb;
    const half* pBl = Bl + (size_t)batch * sB + (size_t)ksl * K + (size_t)n0 * ldb;

    const int NCH = K >> 6;

    float acc[2][8][4];
#pragma unroll
    for (int i = 0; i < 2; i++)
#pragma unroll
        for (int j = 0; j < 8; j++)
#pragma unroll
            for (int t = 0; t < 4; t++) acc[i][j][t] = 0.0f;

    // prologue: stage 0 <- chunk 0
    cp_tile(base, pAh, lda, tid);
    cp_tile(base + 16384, pAl, lda, tid);
    cp_tile(base + 32768, pBh, ldb, tid);
    cp_tile(base + 49152, pBl, ldb, tid);
    asm volatile("cp.async.commit_group;" ::: "memory");

    for (int c = 0; c < NCH; c++) {
        const int st = c & 1;
        if (c + 1 < NCH) {
            const u32 sb = base + (st ^ 1) * 65536;
            const int ko = (c + 1) * 64;
            cp_tile(sb, pAh + ko, lda, tid);
            cp_tile(sb + 16384, pAl + ko, lda, tid);
            cp_tile(sb + 32768, pBh + ko, ldb, tid);
            cp_tile(sb + 49152, pBl + ko, ldb, tid);
        }
        asm volatile("cp.async.commit_group;" ::: "memory");
        asm volatile("cp.async.wait_group 1;" ::: "memory");
        __syncthreads();

        const u32 sAh = base + st * 65536;
        const u32 sAl = sAh + 16384, sBh = sAh + 32768, sBl = sAh + 49152;

#pragma unroll
        for (int ks = 0; ks < 4; ks++) {
            u32 ah[2][4], al[2][4];
#pragma unroll
            for (int mi = 0; mi < 2; mi++) {
                const int row = wm * 32 + mi * 16 + (lane & 15);
                const u32 off = row * 128 + ((((ks << 1) | (lane >> 4)) ^ (row & 7)) << 4);
                ldsm4(ah[mi][0], ah[mi][1], ah[mi][2], ah[mi][3], sAh + off);
                ldsm4(al[mi][0], al[mi][1], al[mi][2], al[mi][3], sAl + off);
            }
            u32 bh[4][4], bl[4][4];
#pragma unroll
            for (int ni = 0; ni < 4; ni++) {
                const int row = wn * 64 + ni * 16 + (lane & 15);
                const u32 off = row * 128 + ((((ks << 1) | (lane >> 4)) ^ (row & 7)) << 4);
                ldsm4(bh[ni][0], bh[ni][1], bh[ni][2], bh[ni][3], sBh + off);
                ldsm4(bl[ni][0], bl[ni][1], bl[ni][2], bl[ni][3], sBl + off);
            }
#pragma unroll
            for (int mi = 0; mi < 2; mi++)
#pragma unroll
                for (int ni = 0; ni < 4; ni++) {
                    mma16816(acc[mi][2 * ni + 0], ah[mi], bh[ni][0], bh[ni][2]);
                    mma16816(acc[mi][2 * ni + 1], ah[mi], bh[ni][1], bh[ni][3]);
                    mma16816(acc[mi][2 * ni + 0], al[mi], bh[ni][0], bh[ni][2]);
                    mma16816(acc[mi][2 * ni + 1], al[mi], bh[ni][1], bh[ni][3]);
                    mma16816(acc[mi][2 * ni + 0], ah[mi], bl[ni][0], bl[ni][2]);
                    mma16816(acc[mi][2 * ni + 1], ah[mi], bl[ni][1], bl[ni][3]);
                }
        }
        __syncthreads();
    }

    // epilogue
    const int mwarp = m0 + wm * 32;
    const int nwarp = n0 + wn * 64;
#pragma unroll
    for (int mi = 0; mi < 2; mi++) {
        const int r0 = mwarp + mi * 16 + (lane >> 2);
        float br0 = 0.f, br1 = 0.f;
        if (BIASROW) { br0 = bias[z * biasZ + r0]; br1 = bias[z * biasZ + r0 + 8]; }
#pragma unroll
        for (int nj = 0; nj < 8; nj++) {
            const int col = nwarp + nj * 8 + (lane & 3) * 2;
            const float* d = acc[mi][nj];
            float v00 = d[0] * scale + br0;
            float v01 = d[1] * scale + br0;
            float v10 = d[2] * scale + br1;
            float v11 = d[3] * scale + br1;
            const size_t i0 = (size_t)z * sC + (size_t)r0 * ldc + col;
            const size_t i1 = i0 + (size_t)8 * ldc;
            if (SPLIT) {
                u32 h, l;
                split2h(v00, v01, h, l);
                *(u32*)(Ch + i0) = h; *(u32*)(Cl + i0) = l;
                split2h(v10, v11, h, l);
                *(u32*)(Ch + i1) = h; *(u32*)(Cl + i1) = l;
            } else {
                *(float2*)(C + i0) = make_float2(v00, v01);
                *(float2*)(C + i1) = make_float2(v10, v11);
            }
        }
    }
}

// ---------------- elementwise kernels ----------------
// split x row + row-sum. one block per (b,c) row of 4096.
__global__ void xsplit_sum(const float* __restrict__ x, half* __restrict__ xh,
                           half* __restrict__ xl, float* __restrict__ sx)
{
    const int r = blockIdx.x, tid = threadIdx.x;
    const float4* in = (const float4*)(x + (size_t)r * TT);
    uint2* oh = (uint2*)(xh + (size_t)r * TT);
    uint2* ol = (uint2*)(xl + (size_t)r * TT);
    float sum = 0.f;
#pragma unroll
    for (int i = 0; i < 4; i++) {
        const int idx = tid + i * 256;
        float4 v = in[idx];
        sum += v.x + v.y + v.z + v.w;
        uint2 h, l;
        split2h(v.x, v.y, h.x, l.x);
        split2h(v.z, v.w, h.y, l.y);
        oh[idx] = h;
        ol[idx] = l;
    }
#pragma unroll
    for (int o = 16; o > 0; o >>= 1) sum += __shfl_xor_sync(~0u, sum, o);
    __shared__ float red[8];
    if ((tid & 31) == 0) red[tid >> 5] = sum;
    __syncthreads();
    if (tid == 0) {
        float t = 0.f;
#pragma unroll
        for (int i = 0; i < 8; i++) t += red[i];
        sx[r] = t;
    }
}

// x [b][c][t] -> xT [b][t][c] f16 hi/lo
__global__ void tsplit_kernel(const float* __restrict__ in, half* __restrict__ oh,
                              half* __restrict__ ol)
{
    __shared__ float t[32][33];
    const int t0 = blockIdx.x * 32, c0 = blockIdx.y * 32, z = blockIdx.z;
    const int tx = threadIdx.x, ty = threadIdx.y;
    const float* inz = in + (size_t)z * CC * TT;
#pragma unroll
    for (int p = 0; p < 4; p++)
        t[ty + p * 8][tx] = inz[(size_t)(c0 + ty + p * 8) * TT + t0 + tx];
    __syncthreads();
    const size_t ob = (size_t)z * TT * CC;
#pragma unroll
    for (int p = 0; p < 4; p++) {
        float v = t[tx][ty + p * 8];
        __half h = __float2half_rn(v);
        __half l = __float2half_rn(v - __half2float(h));
        size_t o = ob + (size_t)(t0 + ty + p * 8) * CC + c0 + tx;
        oh[o] = h;
        ol[o] = l;
    }
}

__global__ void esplit(const float* __restrict__ in, half* __restrict__ oh,
                       half* __restrict__ ol)
{
    size_t i = ((size_t)blockIdx.x * blockDim.x + threadIdx.x) * 4;
    float4 v = *(const float4*)(in + i);
    uint2 h, l;
    split2h(v.x, v.y, h.x, l.x);
    split2h(v.z, v.w, h.y, l.y);
    *(uint2*)(oh + i) = h;
    *(uint2*)(ol + i) = l;
}

// Wv [d][e] -> WvT [e][d] f16 hi/lo
__global__ void wtsplit(const float* __restrict__ in, half* __restrict__ oh,
                        half* __restrict__ ol)
{
    __shared__ float t[32][33];
    const int d0 = blockIdx.x * 32, e0 = blockIdx.y * 32;
    const int tx = threadIdx.x, ty = threadIdx.y;
#pragma unroll
    for (int p = 0; p < 4; p++)
        t[ty + p * 8][tx] = in[(size_t)(d0 + ty + p * 8) * CC + e0 + tx];
    __syncthreads();
#pragma unroll
    for (int p = 0; p < 4; p++) {
        float v = t[tx][ty + p * 8];   // Wv[d0+tx][e0+ty+p*8]
        __half h = __float2half_rn(v);
        __half l = __float2half_rn(v - __half2float(h));
        size_t o = (size_t)(e0 + ty + p * 8) * CC + d0 + tx;
        oh[o] = h;
        ol[o] = l;
    }
}

// sum KSPL_G partials -> G f16 hi/lo
__global__ void gcombine(const float* __restrict__ part, half* __restrict__ gh,
                         half* __restrict__ gl)
{
    size_t i = ((size_t)blockIdx.x * 256 + threadIdx.x) * 4;
    const int b = (int)(i / CCSQ);
    const size_t w = i - (size_t)b * CCSQ;
    const size_t pb = (size_t)b * KSPL_G * CCSQ + w;
    float4 a0 = *(const float4*)(part + pb);
    float4 a1 = *(const float4*)(part + pb + CCSQ);
    float4 a2 = *(const float4*)(part + pb + 2 * CCSQ);
    float4 a3 = *(const float4*)(part + pb + 3 * CCSQ);
    float4 s = make_float4(a0.x + a1.x + a2.x + a3.x, a0.y + a1.y + a2.y + a3.y,
                           a0.z + a1.z + a2.z + a3.z, a0.w + a1.w + a2.w + a3.w);
    uint2 h, l;
    split2h(s.x, s.y, h.x, l.x);
    split2h(s.z, s.w, h.y, l.y);
    *(uint2*)(gh + i) = h;
    *(uint2*)(gl + i) = l;
}

// w1 = Wq*sx, w2 = Wk*sx (per batch). 8 warps/block, one output per warp.
__global__ void matvec_w(const float* __restrict__ Wq, const float* __restrict__ Wk,
                         const float* __restrict__ sx, float* __restrict__ w1,
                         float* __restrict__ w2)
{
    const int w = threadIdx.x >> 5, lane = threadIdx.x & 31;
    const int c = blockIdx.x * 8 + w, b = blockIdx.z;
    const float* W = blockIdx.y ? Wk : Wq;
    float* outp = blockIdx.y ? w2 : w1;
    const float4* Wr = (const float4*)(W + (size_t)c * CC);
    const float4* sv = (const float4*)(sx + b * CC);
    float s = 0.f;
#pragma unroll
    for (int i = 0; i < 4; i++) {
        float4 a = Wr[lane + 32 * i], xv = sv[lane + 32 * i];
        s += a.x * xv.x + a.y * xv.y + a.z * xv.z + a.w * xv.w;
    }
#pragma unroll
    for (int o = 16; o > 0; o >>= 1) s += __shfl_xor_sync(~0u, s, o);
    if (lane == 0) outp[b * CC + c] = s;
}

// softmax with rank-1 corrections + pb = attn*bv + f16 split of attn.
__global__ void softmax_corr(const float* __restrict__ d, const float* __restrict__ w1,
                             const float* __restrict__ w2, const float* __restrict__ bq,
                             const float* __restrict__ bk, const float* __restrict__ bv,
                             half* __restrict__ ah, half* __restrict__ al,
                             float* __restrict__ pb)
{
    const int gw = (blockIdx.x * blockDim.x + threadIdx.x) >> 5;
    const int lane = threadIdx.x & 31;
    const int b = gw >> 9, c = gw & 511;
    const float bqc = bq[c], w1c = w1[b * CC + c];
    const float4* r = (const float4*)(d + (size_t)gw * CC);
    const float4* w2r = (const float4*)(w2 + b * CC);
    const float4* bkr = (const float4*)bk;
    const float4* bvr = (const float4*)bv;

    float4 v[4], bvv[4];
    float mx = -1e30f;
#pragma unroll
    for (int i = 0; i < 4; i++) {
        const int idx = lane + 32 * i;
        float4 dv = r[idx], w2v = w2r[idx], bkv = bkr[idx];
        bvv[i] = bvr[idx];
        v[i].x = dv.x + SCALE_F * (bqc * (w2v.x + (float)TT * bkv.x) + w1c * bkv.x);
        v[i].y = dv.y + SCALE_F * (bqc * (w2v.y + (float)TT * bkv.y) + w1c * bkv.y);
        v[i].z = dv.z + SCALE_F * (bqc * (w2v.z + (float)TT * bkv.z) + w1c * bkv.z);
        v[i].w = dv.w + SCALE_F * (bqc * (w2v.w + (float)TT * bkv.w) + w1c * bkv.w);
        mx = fmaxf(mx, fmaxf(fmaxf(v[i].x, v[i].y), fmaxf(v[i].z, v[i].w)));
    }
#pragma unroll
    for (int o = 16; o > 0; o >>= 1) mx = fmaxf(mx, __shfl_xor_sync(~0u, mx, o));
    float s = 0.f;
#pragma unroll
    for (int i = 0; i < 4; i++) {
        v[i].x = expf(v[i].x - mx); v[i].y = expf(v[i].y - mx);
        v[i].z = expf(v[i].z - mx); v[i].w = expf(v[i].w - mx);
        s += v[i].x + v[i].y + v[i].z + v[i].w;
    }
#pragma unroll
    for (int o = 16; o > 0; o >>= 1) s += __shfl_xor_sync(~0u, s, o);
    const float inv = 1.0f / s;
    float dotbv = 0.f;
#pragma unroll
    for (int i = 0; i < 4; i++) {
        v[i].x *= inv; v[i].y *= inv; v[i].z *= inv; v[i].w *= inv;
        dotbv += v[i].x * bvv[i].x + v[i].y * bvv[i].y + v[i].z * bvv[i].z + v[i].w * bvv[i].w;
        uint2 h, l;
        split2h(v[i].x, v[i].y, h.x, l.x);
        split2h(v[i].z, v[i].w, h.y, l.y);
        size_t o = (size_t)gw * CC + 4 * (lane + 32 * i);
        *(uint2*)(ah + o) = h;
        *(uint2*)(al + o) = l;
    }
#pragma unroll
    for (int o = 16; o > 0; o >>= 1) dotbv += __shfl_xor_sync(~0u, dotbv, o);
    if (lane == 0) pb[gw] = dotbv;
}

// ---------------- launch ----------------
extern "C" void kernel_launch(void* const* d_in, const int* in_sizes, int n_in,
                              void* d_out, int out_size)
{
    (void)in_sizes; (void)n_in; (void)out_size;
    const float* x  = (const float*)d_in[0];
    const float* Wq = (const float*)d_in[1];
    const float* bq = (const float*)d_in[2];
    const float* Wk = (const float*)d_in[3];
    const float* bk = (const float*)d_in[4];
    const float* Wv = (const float*)d_in[5];
    const float* bv = (const float*)d_in[6];
    float* out = (float*)d_out;

    half *xh, *xl, *xTh, *xTl, *wqh, *wql, *wkh, *wkl, *wvTh, *wvTl;
    half *Gh, *Gl, *t2h, *t2l, *aH, *aL, *Ph, *Pl;
    float *part, *dots, *sx, *w1, *w2, *pb;
    cudaGetSymbolAddress((void**)&xh, g_x_h);
    cudaGetSymbolAddress((void**)&xl, g_x_l);
    cudaGetSymbolAddress((void**)&xTh, g_xT_h);
    cudaGetSymbolAddress((void**)&xTl, g_xT_l);
    cudaGetSymbolAddress((void**)&wqh, g_wq_h);
    cudaGetSymbolAddress((void**)&wql, g_wq_l);
    cudaGetSymbolAddress((void**)&wkh, g_wk_h);
    cudaGetSymbolAddress((void**)&wkl, g_wk_l);
    cudaGetSymbolAddress((void**)&wvTh, g_wvT_h);
    cudaGetSymbolAddress((void**)&wvTl, g_wvT_l);
    cudaGetSymbolAddress((void**)&part, g_part);
    cudaGetSymbolAddress((void**)&Gh, g_G_h);
    cudaGetSymbolAddress((void**)&Gl, g_G_l);
    cudaGetSymbolAddress((void**)&t2h, g_t2_h);
    cudaGetSymbolAddress((void**)&t2l, g_t2_l);
    cudaGetSymbolAddress((void**)&dots, g_dots);
    cudaGetSymbolAddress((void**)&aH, g_a_h);
    cudaGetSymbolAddress((void**)&aL, g_a_l);
    cudaGetSymbolAddress((void**)&Ph, g_P_h);
    cudaGetSymbolAddress((void**)&Pl, g_P_l);
    cudaGetSymbolAddress((void**)&sx, g_sx);
    cudaGetSymbolAddress((void**)&w1, g_w1);
    cudaGetSymbolAddress((void**)&w2, g_w2);
    cudaGetSymbolAddress((void**)&pb, g_pb);

    const size_t CT = (size_t)CC * TT;
    const int SMEMSZ = 2 * 65536 + 1024;

    cudaFuncSetAttribute(gemm_mma<false, false, KSPL_G>, cudaFuncAttributeMaxDynamicSharedMemorySize, SMEMSZ);
    cudaFuncSetAttribute(gemm_mma<false, true, 1>, cudaFuncAttributeMaxDynamicSharedMemorySize, SMEMSZ);
    cudaFuncSetAttribute(gemm_mma<false, false, 1>, cudaFuncAttributeMaxDynamicSharedMemorySize, SMEMSZ);
    cudaFuncSetAttribute(gemm_mma<true, false, 1>, cudaFuncAttributeMaxDynamicSharedMemorySize, SMEMSZ);

    // prep
    xsplit_sum<<<BB * CC, 256>>>(x, xh, xl, sx);
    tsplit_kernel<<<dim3(TT / 32, CC / 32, BB), dim3(32, 8)>>>(x, xTh, xTl);
    esplit<<<CCSQ / 1024, 256>>>(Wq, wqh, wql);
    esplit<<<CCSQ / 1024, 256>>>(Wk, wkh, wkl);
    wtsplit<<<dim3(16, 16), dim3(32, 8)>>>(Wv, wvTh, wvTl);
    matvec_w<<<dim3(CC / 8, 2, BB), 256>>>(Wq, Wk, sx, w1, w2);

    // G = x x^T (split-K x4 partials)
    gemm_mma<false, false, KSPL_G><<<dim3(4, 4, BB * KSPL_G), 256, SMEMSZ>>>(
        xh, xl, CT, TT, xh, xl, CT, TT, part, nullptr, nullptr,
        CCSQ, CC, nullptr, 0, 1.0f, TT / KSPL_G);
    gcombine<<<(u32)(BB * CCSQ / 1024), 256>>>(part, Gh, Gl);

    // t2 = Wq * G (uses G symmetry; split f16 out)
    gemm_mma<false, true, 1><<<dim3(4, 4, BB), 256, SMEMSZ>>>(
        wqh, wql, 0, CC, Gh, Gl, CCSQ, CC, nullptr, t2h, t2l,
        CCSQ, CC, nullptr, 0, 1.0f, CC);
    // dots = SCALE * t2 * Wk^T
    gemm_mma<false, false, 1><<<dim3(4, 4, BB), 256, SMEMSZ>>>(
        t2h, t2l, CCSQ, CC, wkh, wkl, 0, CC, dots, nullptr, nullptr,
        CCSQ, CC, nullptr, 0, SCALE_F, CC);
    // softmax + corrections + pb + attn split
    softmax_corr<<<BB * CC / 4, 128>>>(dots, w1, w2, bq, bk, bv, aH, aL, pb);
    // P = attn * Wv (via WvT; split f16 out)
    gemm_mma<false, true, 1><<<dim3(4, 4, BB), 256, SMEMSZ>>>(
        aH, aL, CCSQ, CC, wvTh, wvTl, 0, CC, nullptr, Ph, Pl,
        CCSQ, CC, nullptr, 0, 1.0f, CC);
    // out = P * x + pb (row bias per batch)
    gemm_mma<true, false, 1><<<dim3(TT / 128, CC / 128, BB), 256, SMEMSZ>>>(
        Ph, Pl, CCSQ, CC, xTh, xTl, CT, CC, out, nullptr, nullptr,
        CT, TT, pb, CC, 1.0f, CC);
}

// round 6
// speedup vs baseline: 6.7033x; 1.2381x over previous
#include <cuda_runtime.h>
#include <cuda_fp16.h>

typedef unsigned int u32;

#define BB 8
#define CC 512
#define TT 4096
#define SCALE_F 0.125f
#define NELEM ((size_t)BB * CC * TT)
#define CCSQ ((size_t)CC * CC)
#define KSPL_G 4

// ---------------- scratch ----------------
__device__ half g_x_h[NELEM];
__device__ half g_x_l[NELEM];
__device__ half g_wq_h[CCSQ];
__device__ half g_wq_l[CCSQ];
__device__ half g_wk_h[CCSQ];
__device__ half g_wk_l[CCSQ];
__device__ half g_wv_h[CCSQ];
__device__ half g_wv_l[CCSQ];
__device__ float g_part[(size_t)KSPL_G * BB * CCSQ];
__device__ half g_G_h[(size_t)BB * CCSQ];
__device__ half g_G_l[(size_t)BB * CCSQ];
__device__ half g_t2_h[(size_t)BB * CCSQ];
__device__ half g_t2_l[(size_t)BB * CCSQ];
__device__ float g_dots[(size_t)BB * CCSQ];
__device__ half g_a_h[(size_t)BB * CCSQ];
__device__ half g_a_l[(size_t)BB * CCSQ];
__device__ half g_P_h[(size_t)BB * CCSQ];
__device__ half g_P_l[(size_t)BB * CCSQ];
__device__ float g_sx[BB * CC];
__device__ float g_w1[BB * CC];
__device__ float g_w2[BB * CC];
__device__ float g_pb[BB * CC];

// upper-triangle 128-tile map for G (4x4 tiles -> 10)
__device__ __constant__ int c_ti[10] = {0, 0, 0, 0, 1, 1, 1, 2, 2, 3};
__device__ __constant__ int c_tj[10] = {0, 1, 2, 3, 1, 2, 3, 2, 3, 3};

// ---------------- helpers ----------------
__device__ __forceinline__ u32 smem_u32(const void* p) {
    u32 a;
    asm("{ .reg .u64 t; cvta.to.shared.u64 t, %1; cvt.u32.u64 %0, t; }" : "=r"(a) : "l"(p));
    return a;
}
__device__ __forceinline__ void split2h(float a, float b, u32& h, u32& l) {
    __half h0 = __float2half_rn(a), h1 = __float2half_rn(b);
    __half l0 = __float2half_rn(a - __half2float(h0));
    __half l1 = __float2half_rn(b - __half2float(h1));
    __half2 hh = __halves2half2(h0, h1), ll = __halves2half2(l0, l1);
    h = *(u32*)&hh;
    l = *(u32*)&ll;
}
__device__ __forceinline__ void ldsm4(u32& r0, u32& r1, u32& r2, u32& r3, u32 addr) {
    asm volatile("ldmatrix.sync.aligned.m8n8.x4.shared.b16 {%0,%1,%2,%3}, [%4];"
                 : "=r"(r0), "=r"(r1), "=r"(r2), "=r"(r3) : "r"(addr));
}
__device__ __forceinline__ void ldsm4t(u32& r0, u32& r1, u32& r2, u32& r3, u32 addr) {
    asm volatile("ldmatrix.sync.aligned.m8n8.x4.trans.shared.b16 {%0,%1,%2,%3}, [%4];"
                 : "=r"(r0), "=r"(r1), "=r"(r2), "=r"(r3) : "r"(addr));
}
__device__ __forceinline__ void mma16816(float* d, const u32* a, u32 b0, u32 b1) {
    asm volatile(
        "mma.sync.aligned.m16n8k16.row.col.f32.f16.f16.f32 "
        "{%0,%1,%2,%3}, {%4,%5,%6,%7}, {%8,%9}, {%0,%1,%2,%3};"
        : "+f"(d[0]), "+f"(d[1]), "+f"(d[2]), "+f"(d[3])
        : "r"(a[0]), "r"(a[1]), "r"(a[2]), "r"(a[3]), "r"(b0), "r"(b1));
}
// cp.async 128 rows x 64 half (128B rows), SW swizzle; 256 threads.
__device__ __forceinline__ void cp_tile(u32 sdst, const half* g, int ld, int tid) {
    const int seg = tid & 7;
    const int r0 = tid >> 3;
    const char* gc = (const char*)g + seg * 16;
#pragma unroll
    for (int p = 0; p < 4; p++) {
        int row = p * 32 + r0;
        u32 dst = sdst + row * 128 + ((seg ^ (row & 7)) << 4);
        const void* src = gc + (size_t)row * ld * sizeof(half);
        asm volatile("cp.async.cg.shared.global [%0], [%1], 16;" :: "r"(dst), "l"(src) : "memory");
    }
}
// cp.async 64 rows x 128 half (256B rows), swizzle low-3 of 16B chunk; 256 threads.
__device__ __forceinline__ void cp_tileB(u32 sdst, const half* g, int ld, int tid) {
    const int seg = tid & 15;
    const int r0 = tid >> 4;
    const char* gc = (const char*)g + seg * 16;
#pragma unroll
    for (int p = 0; p < 4; p++) {
        int row = p * 16 + r0;
        u32 dst = sdst + row * 256 + ((seg ^ (row & 7)) << 4);
        const void* src = gc + (size_t)row * ld * sizeof(half);
        asm volatile("cp.async.cg.shared.global [%0], [%1], 16;" :: "r"(dst), "l"(src) : "memory");
    }
}

// ---------------------------------------------------------------------------
// GEMM D[m,n] = scale*(A.B) + bias; fp16 2-term split, 3 products with
// fragment reuse. BM=BN=128, BK=64. 8 warps (4M x 2N). 2-stage cp.async.
// BTRANS=false: B is NT ([n][k], k-contig).  BTRANS=true: B is NN ([k][n],
// n-contig, row stride ldb) loaded via ldmatrix.trans.
// TRI: grid.x indexes upper-triangle 128-tiles (G = x x^T symmetry).
// ---------------------------------------------------------------------------
template <bool BIASROW, bool SPLIT, int KSPL, bool TRI, bool BTRANS>
__global__ __launch_bounds__(256) void gemm_mma(
    const half* __restrict__ Ah, const half* __restrict__ Al, size_t sA, int lda,
    const half* __restrict__ Bh, const half* __restrict__ Bl, size_t sB, int ldb,
    float* __restrict__ C, half* __restrict__ Ch, half* __restrict__ Cl,
    size_t sC, int ldc, const float* __restrict__ bias, int biasZ,
    float scale, int K)
{
    extern __shared__ char dyn[];
    char* dg = (char*)(((size_t)dyn + 1023) & ~(size_t)1023);
    const u32 base = smem_u32(dg);    // 2 stages x 64KB (Ah,Al,Bh,Bl 16KB)

    const int tid = threadIdx.x, wid = tid >> 5, lane = tid & 31;
    const int z = blockIdx.z;
    const int batch = z / KSPL, ksl = z - batch * KSPL;
    const int m0 = TRI ? c_ti[blockIdx.x] * 128 : blockIdx.y * 128;
    const int n0 = TRI ? c_tj[blockIdx.x] * 128 : blockIdx.x * 128;
    const int wm = wid & 3, wn = wid >> 2;

    const half* pAh = Ah + (size_t)batch * sA + (size_t)ksl * K + (size_t)m0 * lda;
    const half* pAl = Al + (size_t)batch * sA + (size_t)ksl * K + (size_t)m0 * lda;
    const half* pBh;
    const half* pBl;
    if (BTRANS) {
        pBh = Bh + (size_t)batch * sB + (size_t)(ksl * K) * ldb + n0;
        pBl = Bl + (size_t)batch * sB + (size_t)(ksl * K) * ldb + n0;
    } else {
        pBh = Bh + (size_t)batch * sB + (size_t)ksl * K + (size_t)n0 * ldb;
        pBl = Bl + (size_t)batch * sB + (size_t)ksl * K + (size_t)n0 * ldb;
    }

    const int NCH = K >> 6;

    float acc[2][8][4];
#pragma unroll
    for (int i = 0; i < 2; i++)
#pragma unroll
        for (int j = 0; j < 8; j++)
#pragma unroll
            for (int t = 0; t < 4; t++) acc[i][j][t] = 0.0f;

    // prologue
    cp_tile(base, pAh, lda, tid);
    cp_tile(base + 16384, pAl, lda, tid);
    if (BTRANS) {
        cp_tileB(base + 32768, pBh, ldb, tid);
        cp_tileB(base + 49152, pBl, ldb, tid);
    } else {
        cp_tile(base + 32768, pBh, ldb, tid);
        cp_tile(base + 49152, pBl, ldb, tid);
    }
    asm volatile("cp.async.commit_group;" ::: "memory");

    for (int c = 0; c < NCH; c++) {
        const int st = c & 1;
        if (c + 1 < NCH) {
            const u32 sb = base + (st ^ 1) * 65536;
            const int ko = (c + 1) * 64;
            cp_tile(sb, pAh + ko, lda, tid);
            cp_tile(sb + 16384, pAl + ko, lda, tid);
            if (BTRANS) {
                cp_tileB(sb + 32768, pBh + (size_t)ko * ldb, ldb, tid);
                cp_tileB(sb + 49152, pBl + (size_t)ko * ldb, ldb, tid);
            } else {
                cp_tile(sb + 32768, pBh + ko, ldb, tid);
                cp_tile(sb + 49152, pBl + ko, ldb, tid);
            }
        }
        asm volatile("cp.async.commit_group;" ::: "memory");
        asm volatile("cp.async.wait_group 1;" ::: "memory");
        __syncthreads();

        const u32 sAh = base + st * 65536;
        const u32 sAl = sAh + 16384, sBh = sAh + 32768, sBl = sAh + 49152;

#pragma unroll
        for (int ks = 0; ks < 4; ks++) {
            u32 ah[2][4], al[2][4];
#pragma unroll
            for (int mi = 0; mi < 2; mi++) {
                const int row = wm * 32 + mi * 16 + (lane & 15);
                const u32 off = row * 128 + ((((ks << 1) | (lane >> 4)) ^ (row & 7)) << 4);
                ldsm4(ah[mi][0], ah[mi][1], ah[mi][2], ah[mi][3], sAh + off);
                ldsm4(al[mi][0], al[mi][1], al[mi][2], al[mi][3], sAl + off);
            }
            u32 bh[4][4], bl[4][4];
#pragma unroll
            for (int ni = 0; ni < 4; ni++) {
                if (BTRANS) {
                    const int row = ks * 16 + (lane & 15);
                    const int chunk = wn * 8 + ni * 2 + (lane >> 4);
                    const u32 off = row * 256 + ((chunk ^ (row & 7)) << 4);
                    ldsm4t(bh[ni][0], bh[ni][1], bh[ni][2], bh[ni][3], sBh + off);
                    ldsm4t(bl[ni][0], bl[ni][1], bl[ni][2], bl[ni][3], sBl + off);
                } else {
                    const int row = wn * 64 + ni * 16 + (lane & 15);
                    const u32 off = row * 128 + ((((ks << 1) | (lane >> 4)) ^ (row & 7)) << 4);
                    ldsm4(bh[ni][0], bh[ni][1], bh[ni][2], bh[ni][3], sBh + off);
                    ldsm4(bl[ni][0], bl[ni][1], bl[ni][2], bl[ni][3], sBl + off);
                }
            }
            const int p0 = BTRANS ? 1 : 2;   // khi fragment index
            const int q0 = BTRANS ? 2 : 1;   // n+8 fragment base
#pragma unroll
            for (int mi = 0; mi < 2; mi++)
#pragma unroll
                for (int ni = 0; ni < 4; ni++) {
                    mma16816(acc[mi][2 * ni + 0], ah[mi], bh[ni][0], bh[ni][p0]);
                    mma16816(acc[mi][2 * ni + 1], ah[mi], bh[ni][q0], bh[ni][3]);
                    mma16816(acc[mi][2 * ni + 0], al[mi], bh[ni][0], bh[ni][p0]);
                    mma16816(acc[mi][2 * ni + 1], al[mi], bh[ni][q0], bh[ni][3]);
                    mma16816(acc[mi][2 * ni + 0], ah[mi], bl[ni][0], bl[ni][p0]);
                    mma16816(acc[mi][2 * ni + 1], ah[mi], bl[ni][q0], bl[ni][3]);
                }
        }
        __syncthreads();
    }

    // epilogue
    const int mwarp = m0 + wm * 32;
    const int nwarp = n0 + wn * 64;
#pragma unroll
    for (int mi = 0; mi < 2; mi++) {
        const int r0 = mwarp + mi * 16 + (lane >> 2);
        float br0 = 0.f, br1 = 0.f;
        if (BIASROW) { br0 = bias[z * biasZ + r0]; br1 = bias[z * biasZ + r0 + 8]; }
#pragma unroll
        for (int nj = 0; nj < 8; nj++) {
            const int col = nwarp + nj * 8 + (lane & 3) * 2;
            const float* d = acc[mi][nj];
            float v00 = d[0] * scale + br0;
            float v01 = d[1] * scale + br0;
            float v10 = d[2] * scale + br1;
            float v11 = d[3] * scale + br1;
            const size_t i0 = (size_t)z * sC + (size_t)r0 * ldc + col;
            const size_t i1 = i0 + (size_t)8 * ldc;
            if (SPLIT) {
                u32 h, l;
                split2h(v00, v01, h, l);
                *(u32*)(Ch + i0) = h; *(u32*)(Cl + i0) = l;
                split2h(v10, v11, h, l);
                *(u32*)(Ch + i1) = h; *(u32*)(Cl + i1) = l;
            } else {
                *(float2*)(C + i0) = make_float2(v00, v01);
                *(float2*)(C + i1) = make_float2(v10, v11);
            }
        }
    }
}

// ---------------- elementwise kernels ----------------
__global__ void xsplit_sum(const float* __restrict__ x, half* __restrict__ xh,
                           half* __restrict__ xl, float* __restrict__ sx)
{
    const int r = blockIdx.x, tid = threadIdx.x;
    const float4* in = (const float4*)(x + (size_t)r * TT);
    uint2* oh = (uint2*)(xh + (size_t)r * TT);
    uint2* ol = (uint2*)(xl + (size_t)r * TT);
    float sum = 0.f;
#pragma unroll
    for (int i = 0; i < 4; i++) {
        const int idx = tid + i * 256;
        float4 v = in[idx];
        sum += v.x + v.y + v.z + v.w;
        uint2 h, l;
        split2h(v.x, v.y, h.x, l.x);
        split2h(v.z, v.w, h.y, l.y);
        oh[idx] = h;
        ol[idx] = l;
    }
#pragma unroll
    for (int o = 16; o > 0; o >>= 1) sum += __shfl_xor_sync(~0u, sum, o);
    __shared__ float red[8];
    if ((tid & 31) == 0) red[tid >> 5] = sum;
    __syncthreads();
    if (tid == 0) {
        float t = 0.f;
#pragma unroll
        for (int i = 0; i < 8; i++) t += red[i];
        sx[r] = t;
    }
}

__global__ void esplit(const float* __restrict__ in, half* __restrict__ oh,
                       half* __restrict__ ol)
{
    size_t i = ((size_t)blockIdx.x * blockDim.x + threadIdx.x) * 4;
    float4 v = *(const float4*)(in + i);
    uint2 h, l;
    split2h(v.x, v.y, h.x, l.x);
    split2h(v.z, v.w, h.y, l.y);
    *(uint2*)(oh + i) = h;
    *(uint2*)(ol + i) = l;
}

// sum KSPL_G partials over upper-tri tiles -> G f16 hi/lo, with mirror.
// grid: x = 16 (4x4 sub 32x32), y = 10 tri tiles, z = batch. block 32x8.
__global__ void gcombine_sym(const float* __restrict__ part, half* __restrict__ gh,
                             half* __restrict__ gl)
{
    __shared__ float t[32][33];
    const int ti = c_ti[blockIdx.y], tj = c_tj[blockIdx.y];
    const int sxo = (blockIdx.x & 3) * 32, syo = (blockIdx.x >> 2) * 32;
    const int b = blockIdx.z;
    const int r0 = ti * 128 + syo, c0 = tj * 128 + sxo;
    const int tx = threadIdx.x, ty = threadIdx.y;
    const float* pz = part + (size_t)b * KSPL_G * CCSQ;
    half* ghb = gh + (size_t)b * CCSQ;
    half* glb = gl + (size_t)b * CCSQ;
#pragma unroll
    for (int p = 0; p < 4; p++) {
        const int r = r0 + ty + p * 8;
        const size_t w = (size_t)r * CC + c0 + tx;
        float s = pz[w] + pz[w + CCSQ] + pz[w + 2 * CCSQ] + pz[w + 3 * CCSQ];
        t[ty + p * 8][tx] = s;
        __half h = __float2half_rn(s);
        ghb[w] = h;
        glb[w] = __float2half_rn(s - __half2float(h));
    }
    if (ti != tj) {
        __syncthreads();
#pragma unroll
        for (int p = 0; p < 4; p++) {
            float s = t[tx][ty + p * 8];
            const size_t w = (size_t)(c0 + ty + p * 8) * CC + r0 + tx;
            __half h = __float2half_rn(s);
            ghb[w] = h;
            glb[w] = __float2half_rn(s - __half2float(h));
        }
    }
}

// w1 = Wq*sx, w2 = Wk*sx per batch
__global__ void matvec_w(const float* __restrict__ Wq, const float* __restrict__ Wk,
                         const float* __restrict__ sx, float* __restrict__ w1,
                         float* __restrict__ w2)
{
    const int w = threadIdx.x >> 5, lane = threadIdx.x & 31;
    const int c = blockIdx.x * 8 + w, b = blockIdx.z;
    const float* W = blockIdx.y ? Wk : Wq;
    float* outp = blockIdx.y ? w2 : w1;
    const float4* Wr = (const float4*)(W + (size_t)c * CC);
    const float4* sv = (const float4*)(sx + b * CC);
    float s = 0.f;
#pragma unroll
    for (int i = 0; i < 4; i++) {
        float4 a = Wr[lane + 32 * i], xv = sv[lane + 32 * i];
        s += a.x * xv.x + a.y * xv.y + a.z * xv.z + a.w * xv.w;
    }
#pragma unroll
    for (int o = 16; o > 0; o >>= 1) s += __shfl_xor_sync(~0u, s, o);
    if (lane == 0) outp[b * CC + c] = s;
}

// softmax + rank-1 corrections + pb = attn*bv + f16 split of attn
__global__ void softmax_corr(const float* __restrict__ d, const float* __restrict__ w1,
                             const float* __restrict__ w2, const float* __restrict__ bq,
                             const float* __restrict__ bk, const float* __restrict__ bv,
                             half* __restrict__ ah, half* __restrict__ al,
                             float* __restrict__ pb)
{
    const int gw = (blockIdx.x * blockDim.x + threadIdx.x) >> 5;
    const int lane = threadIdx.x & 31;
    const int b = gw >> 9, c = gw & 511;
    const float bqc = bq[c], w1c = w1[b * CC + c];
    const float4* r = (const float4*)(d + (size_t)gw * CC);
    const float4* w2r = (const float4*)(w2 + b * CC);
    const float4* bkr = (const float4*)bk;
    const float4* bvr = (const float4*)bv;

    float4 v[4], bvv[4];
    float mx = -1e30f;
#pragma unroll
    for (int i = 0; i < 4; i++) {
        const int idx = lane + 32 * i;
        float4 dv = r[idx], w2v = w2r[idx], bkv = bkr[idx];
        bvv[i] = bvr[idx];
        v[i].x = dv.x + SCALE_F * (bqc * (w2v.x + (float)TT * bkv.x) + w1c * bkv.x);
        v[i].y = dv.y + SCALE_F * (bqc * (w2v.y + (float)TT * bkv.y) + w1c * bkv.y);
        v[i].z = dv.z + SCALE_F * (bqc * (w2v.z + (float)TT * bkv.z) + w1c * bkv.z);
        v[i].w = dv.w + SCALE_F * (bqc * (w2v.w + (float)TT * bkv.w) + w1c * bkv.w);
        mx = fmaxf(mx, fmaxf(fmaxf(v[i].x, v[i].y), fmaxf(v[i].z, v[i].w)));
    }
#pragma unroll
    for (int o = 16; o > 0; o >>= 1) mx = fmaxf(mx, __shfl_xor_sync(~0u, mx, o));
    float s = 0.f;
#pragma unroll
    for (int i = 0; i < 4; i++) {
        v[i].x = expf(v[i].x - mx); v[i].y = expf(v[i].y - mx);
        v[i].z = expf(v[i].z - mx); v[i].w = expf(v[i].w - mx);
        s += v[i].x + v[i].y + v[i].z + v[i].w;
    }
#pragma unroll
    for (int o = 16; o > 0; o >>= 1) s += __shfl_xor_sync(~0u, s, o);
    const float inv = 1.0f / s;
    float dotbv = 0.f;
#pragma unroll
    for (int i = 0; i < 4; i++) {
        v[i].x *= inv; v[i].y *= inv; v[i].z *= inv; v[i].w *= inv;
        dotbv += v[i].x * bvv[i].x + v[i].y * bvv[i].y + v[i].z * bvv[i].z + v[i].w * bvv[i].w;
        uint2 h, l;
        split2h(v[i].x, v[i].y, h.x, l.x);
        split2h(v[i].z, v[i].w, h.y, l.y);
        size_t o = (size_t)gw * CC + 4 * (lane + 32 * i);
        *(uint2*)(ah + o) = h;
        *(uint2*)(al + o) = l;
    }
#pragma unroll
    for (int o = 16; o > 0; o >>= 1) dotbv += __shfl_xor_sync(~0u, dotbv, o);
    if (lane == 0) pb[gw] = dotbv;
}

// ---------------- launch ----------------
extern "C" void kernel_launch(void* const* d_in, const int* in_sizes, int n_in,
                              void* d_out, int out_size)
{
    (void)in_sizes; (void)n_in; (void)out_size;
    const float* x  = (const float*)d_in[0];
    const float* Wq = (const float*)d_in[1];
    const float* bq = (const float*)d_in[2];
    const float* Wk = (const float*)d_in[3];
    const float* bk = (const float*)d_in[4];
    const float* Wv = (const float*)d_in[5];
    const float* bv = (const float*)d_in[6];
    float* out = (float*)d_out;

    half *xh, *xl, *wqh, *wql, *wkh, *wkl, *wvh, *wvl;
    half *Gh, *Gl, *t2h, *t2l, *aH, *aL, *Ph, *Pl;
    float *part, *dots, *sx, *w1, *w2, *pb;
    cudaGetSymbolAddress((void**)&xh, g_x_h);
    cudaGetSymbolAddress((void**)&xl, g_x_l);
    cudaGetSymbolAddress((void**)&wqh, g_wq_h);
    cudaGetSymbolAddress((void**)&wql, g_wq_l);
    cudaGetSymbolAddress((void**)&wkh, g_wk_h);
    cudaGetSymbolAddress((void**)&wkl, g_wk_l);
    cudaGetSymbolAddress((void**)&wvh, g_wv_h);
    cudaGetSymbolAddress((void**)&wvl, g_wv_l);
    cudaGetSymbolAddress((void**)&part, g_part);
    cudaGetSymbolAddress((void**)&Gh, g_G_h);
    cudaGetSymbolAddress((void**)&Gl, g_G_l);
    cudaGetSymbolAddress((void**)&t2h, g_t2_h);
    cudaGetSymbolAddress((void**)&t2l, g_t2_l);
    cudaGetSymbolAddress((void**)&dots, g_dots);
    cudaGetSymbolAddress((void**)&aH, g_a_h);
    cudaGetSymbolAddress((void**)&aL, g_a_l);
    cudaGetSymbolAddress((void**)&Ph, g_P_h);
    cudaGetSymbolAddress((void**)&Pl, g_P_l);
    cudaGetSymbolAddress((void**)&sx, g_sx);
    cudaGetSymbolAddress((void**)&w1, g_w1);
    cudaGetSymbolAddress((void**)&w2, g_w2);
    cudaGetSymbolAddress((void**)&pb, g_pb);

    const size_t CT = (size_t)CC * TT;
    const int SMEMSZ = 2 * 65536 + 1024;

    cudaFuncSetAttribute(gemm_mma<false, false, KSPL_G, true, false>, cudaFuncAttributeMaxDynamicSharedMemorySize, SMEMSZ);
    cudaFuncSetAttribute(gemm_mma<false, true, 1, false, false>, cudaFuncAttributeMaxDynamicSharedMemorySize, SMEMSZ);
    cudaFuncSetAttribute(gemm_mma<false, false, 1, false, false>, cudaFuncAttributeMaxDynamicSharedMemorySize, SMEMSZ);
    cudaFuncSetAttribute(gemm_mma<false, true, 1, false, true>, cudaFuncAttributeMaxDynamicSharedMemorySize, SMEMSZ);
    cudaFuncSetAttribute(gemm_mma<true, false, 1, false, true>, cudaFuncAttributeMaxDynamicSharedMemorySize, SMEMSZ);

    // prep
    xsplit_sum<<<BB * CC, 256>>>(x, xh, xl, sx);
    esplit<<<CCSQ / 1024, 256>>>(Wq, wqh, wql);
    esplit<<<CCSQ / 1024, 256>>>(Wk, wkh, wkl);
    esplit<<<CCSQ / 1024, 256>>>(Wv, wvh, wvl);
    matvec_w<<<dim3(CC / 8, 2, BB), 256>>>(Wq, Wk, sx, w1, w2);

    // G = x x^T : upper-triangle tiles only, split-K x4 partials
    gemm_mma<false, false, KSPL_G, true, false><<<dim3(10, 1, BB * KSPL_G), 256, SMEMSZ>>>(
        xh, xl, CT, TT, xh, xl, CT, TT, part, nullptr, nullptr,
        CCSQ, CC, nullptr, 0, 1.0f, TT / KSPL_G);
    gcombine_sym<<<dim3(16, 10, BB), dim3(32, 8)>>>(part, Gh, Gl);

    // t2 = Wq * G (G symmetric -> NT with B=G)
    gemm_mma<false, true, 1, false, false><<<dim3(4, 4, BB), 256, SMEMSZ>>>(
        wqh, wql, 0, CC, Gh, Gl, CCSQ, CC, nullptr, t2h, t2l,
        CCSQ, CC, nullptr, 0, 1.0f, CC);
    // dots = SCALE * t2 * Wk^T
    gemm_mma<false, false, 1, false, false><<<dim3(4, 4, BB), 256, SMEMSZ>>>(
        t2h, t2l, CCSQ, CC, wkh, wkl, 0, CC, dots, nullptr, nullptr,
        CCSQ, CC, nullptr, 0, SCALE_F, CC);
    // softmax + corrections + pb + attn split
    softmax_corr<<<BB * CC / 4, 128>>>(dots, w1, w2, bq, bk, bv, aH, aL, pb);
    // P = attn * Wv   (B = Wv [d][e], NN via ldmatrix.trans)
    gemm_mma<false, true, 1, false, true><<<dim3(4, 4, BB), 256, SMEMSZ>>>(
        aH, aL, CCSQ, CC, wvh, wvl, 0, CC, nullptr, Ph, Pl,
        CCSQ, CC, nullptr, 0, 1.0f, CC);
    // out = P * x + pb  (B = x [c][t], NN via ldmatrix.trans)
    gemm_mma<true, false, 1, false, true><<<dim3(TT / 128, CC / 128, BB), 256, SMEMSZ>>>(
        Ph, Pl, CCSQ, CC, xh, xl, CT, TT, out, nullptr, nullptr,
        CT, TT, pb, CC, 1.0f, CC);
}

// round 8
// speedup vs baseline: 7.6332x; 1.1387x over previous
#include <cuda_runtime.h>
#include <cuda_fp16.h>

typedef unsigned int u32;

#define BB 8
#define CC 512
#define TT 4096
#define SCALE_F 0.125f
#define NELEM ((size_t)BB * CC * TT)
#define CCSQ ((size_t)CC * CC)
#define KSPL_G 4

// ---------------- scratch ----------------
__device__ half g_x_h[NELEM];
__device__ half g_x_l[NELEM];
__device__ half g_wq_h[CCSQ];
__device__ half g_wq_l[CCSQ];
__device__ half g_wk_h[CCSQ];
__device__ half g_wk_l[CCSQ];
__device__ half g_wv_h[CCSQ];
__device__ half g_wv_l[CCSQ];
__device__ float g_part[(size_t)KSPL_G * BB * CCSQ];
__device__ half g_G_h[(size_t)BB * CCSQ];
__device__ half g_G_l[(size_t)BB * CCSQ];
__device__ half g_t2_h[(size_t)BB * CCSQ];
__device__ half g_t2_l[(size_t)BB * CCSQ];
__device__ float g_dots[(size_t)BB * CCSQ];
__device__ half g_a_h[(size_t)BB * CCSQ];
__device__ half g_a_l[(size_t)BB * CCSQ];
__device__ half g_P_h[(size_t)BB * CCSQ];
__device__ half g_P_l[(size_t)BB * CCSQ];
__device__ float g_sx[BB * CC];
__device__ float g_w1[BB * CC];
__device__ float g_w2[BB * CC];
__device__ float g_pb[BB * CC];

// upper-triangle 128-tile map for G (4x4 tiles -> 10)
__device__ __constant__ int c_ti[10] = {0, 0, 0, 0, 1, 1, 1, 2, 2, 3};
__device__ __constant__ int c_tj[10] = {0, 1, 2, 3, 1, 2, 3, 2, 3, 3};

// ---------------- helpers ----------------
__device__ __forceinline__ u32 smem_u32(const void* p) {
    u32 a;
    asm("{ .reg .u64 t; cvta.to.shared.u64 t, %1; cvt.u32.u64 %0, t; }" : "=r"(a) : "l"(p));
    return a;
}
__device__ __forceinline__ void split2h(float a, float b, u32& h, u32& l) {
    __half h0 = __float2half_rn(a), h1 = __float2half_rn(b);
    __half l0 = __float2half_rn(a - __half2float(h0));
    __half l1 = __float2half_rn(b - __half2float(h1));
    __half2 hh = __halves2half2(h0, h1), ll = __halves2half2(l0, l1);
    h = *(u32*)&hh;
    l = *(u32*)&ll;
}
__device__ __forceinline__ void ldsm4(u32& r0, u32& r1, u32& r2, u32& r3, u32 addr) {
    asm volatile("ldmatrix.sync.aligned.m8n8.x4.shared.b16 {%0,%1,%2,%3}, [%4];"
                 : "=r"(r0), "=r"(r1), "=r"(r2), "=r"(r3) : "r"(addr));
}
__device__ __forceinline__ void ldsm4t(u32& r0, u32& r1, u32& r2, u32& r3, u32 addr) {
    asm volatile("ldmatrix.sync.aligned.m8n8.x4.trans.shared.b16 {%0,%1,%2,%3}, [%4];"
                 : "=r"(r0), "=r"(r1), "=r"(r2), "=r"(r3) : "r"(addr));
}
__device__ __forceinline__ void mma16816(float* d, const u32* a, u32 b0, u32 b1) {
    asm volatile(
        "mma.sync.aligned.m16n8k16.row.col.f32.f16.f16.f32 "
        "{%0,%1,%2,%3}, {%4,%5,%6,%7}, {%8,%9}, {%0,%1,%2,%3};"
        : "+f"(d[0]), "+f"(d[1]), "+f"(d[2]), "+f"(d[3])
        : "r"(a[0]), "r"(a[1]), "r"(a[2]), "r"(a[3]), "r"(b0), "r"(b1));
}
// cp.async 128 rows x 64 half (128B rows), SW swizzle; 256 threads.
__device__ __forceinline__ void cp_tile(u32 sdst, const half* g, int ld, int tid) {
    const int seg = tid & 7;
    const int r0 = tid >> 3;
    const char* gc = (const char*)g + seg * 16;
#pragma unroll
    for (int p = 0; p < 4; p++) {
        int row = p * 32 + r0;
        u32 dst = sdst + row * 128 + ((seg ^ (row & 7)) << 4);
        const void* src = gc + (size_t)row * ld * sizeof(half);
        asm volatile("cp.async.cg.shared.global [%0], [%1], 16;" :: "r"(dst), "l"(src) : "memory");
    }
}
// cp.async 64 rows x 128 half (256B rows), swizzle low-3 of 16B chunk; 256 threads.
__device__ __forceinline__ void cp_tileB(u32 sdst, const half* g, int ld, int tid) {
    const int seg = tid & 15;
    const int r0 = tid >> 4;
    const char* gc = (const char*)g + seg * 16;
#pragma unroll
    for (int p = 0; p < 4; p++) {
        int row = p * 16 + r0;
        u32 dst = sdst + row * 256 + ((seg ^ (row & 7)) << 4);
        const void* src = gc + (size_t)row * ld * sizeof(half);
        asm volatile("cp.async.cg.shared.global [%0], [%1], 16;" :: "r"(dst), "l"(src) : "memory");
    }
}

// ---------------------------------------------------------------------------
// GEMM D[m,n] = scale*(A.B) + bias; fp16 2-term split.
// NPROD=3: AhBh + AlBh + AhBl (full bilinear minus AlBl).
// NPROD=2: AhBh + AlBh (drops AhBl; B-lo never loaded). Linear-path only.
// BM=BN=128, BK=64. 8 warps (4M x 2N). 2-stage cp.async.
// BTRANS=false: B is NT ([n][k], k-contig). BTRANS=true: B is NN ([k][n])
// via ldmatrix.trans. TRI: grid.x walks upper-triangle tiles (G symmetry).
// ---------------------------------------------------------------------------
template <bool BIASROW, bool SPLIT, int KSPL, bool TRI, bool BTRANS, int NPROD>
__global__ __launch_bounds__(256) void gemm_mma(
    const half* __restrict__ Ah, const half* __restrict__ Al, size_t sA, int lda,
    const half* __restrict__ Bh, const half* __restrict__ Bl, size_t sB, int ldb,
    float* __restrict__ C, half* __restrict__ Ch, half* __restrict__ Cl,
    size_t sC, int ldc, const float* __restrict__ bias, int biasZ,
    float scale, int K)
{
    extern __shared__ char dyn[];
    char* dg = (char*)(((size_t)dyn + 1023) & ~(size_t)1023);
    const u32 base = smem_u32(dg);

    const int tid = threadIdx.x, wid = tid >> 5, lane = tid & 31;
    const int z = blockIdx.z;
    const int batch = z / KSPL, ksl = z - batch * KSPL;
    const int m0 = TRI ? c_ti[blockIdx.x] * 128 : blockIdx.y * 128;
    const int n0 = TRI ? c_tj[blockIdx.x] * 128 : blockIdx.x * 128;
    const int wm = wid & 3, wn = wid >> 2;

    const half* pAh = Ah + (size_t)batch * sA + (size_t)ksl * K + (size_t)m0 * lda;
    const half* pAl = Al + (size_t)batch * sA + (size_t)ksl * K + (size_t)m0 * lda;
    const half* pBh;
    const half* pBl;
    if (BTRANS) {
        pBh = Bh + (size_t)batch * sB + (size_t)(ksl * K) * ldb + n0;
        pBl = Bl + (size_t)batch * sB + (size_t)(ksl * K) * ldb + n0;
    } else {
        pBh = Bh + (size_t)batch * sB + (size_t)ksl * K + (size_t)n0 * ldb;
        pBl = Bl + (size_t)batch * sB + (size_t)ksl * K + (size_t)n0 * ldb;
    }

    const int NCH = K >> 6;

    float acc[2][8][4];
#pragma unroll
    for (int i = 0; i < 2; i++)
#pragma unroll
        for (int j = 0; j < 8; j++)
#pragma unroll
            for (int t = 0; t < 4; t++) acc[i][j][t] = 0.0f;

    // prologue
    cp_tile(base, pAh, lda, tid);
    cp_tile(base + 16384, pAl, lda, tid);
    if (BTRANS) {
        cp_tileB(base + 32768, pBh, ldb, tid);
        if (NPROD == 3) cp_tileB(base + 49152, pBl, ldb, tid);
    } else {
        cp_tile(base + 32768, pBh, ldb, tid);
        if (NPROD == 3) cp_tile(base + 49152, pBl, ldb, tid);
    }
    asm volatile("cp.async.commit_group;" ::: "memory");

    for (int c = 0; c < NCH; c++) {
        const int st = c & 1;
        if (c + 1 < NCH) {
            const u32 sb = base + (st ^ 1) * 65536;
            const int ko = (c + 1) * 64;
            cp_tile(sb, pAh + ko, lda, tid);
            cp_tile(sb + 16384, pAl + ko, lda, tid);
            if (BTRANS) {
                cp_tileB(sb + 32768, pBh + (size_t)ko * ldb, ldb, tid);
                if (NPROD == 3) cp_tileB(sb + 49152, pBl + (size_t)ko * ldb, ldb, tid);
            } else {
                cp_tile(sb + 32768, pBh + ko, ldb, tid);
                if (NPROD == 3) cp_tile(sb + 49152, pBl + ko, ldb, tid);
            }
        }
        asm volatile("cp.async.commit_group;" ::: "memory");
        asm volatile("cp.async.wait_group 1;" ::: "memory");
        __syncthreads();

        const u32 sAh = base + st * 65536;
        const u32 sAl = sAh + 16384, sBh = sAh + 32768, sBl = sAh + 49152;

#pragma unroll
        for (int ks = 0; ks < 4; ks++) {
            u32 ah[2][4], al[2][4];
#pragma unroll
            for (int mi = 0; mi < 2; mi++) {
                const int row = wm * 32 + mi * 16 + (lane & 15);
                const u32 off = row * 128 + ((((ks << 1) | (lane >> 4)) ^ (row & 7)) << 4);
                ldsm4(ah[mi][0], ah[mi][1], ah[mi][2], ah[mi][3], sAh + off);
                ldsm4(al[mi][0], al[mi][1], al[mi][2], al[mi][3], sAl + off);
            }
            u32 bh[4][4], bl[4][4];
#pragma unroll
            for (int ni = 0; ni < 4; ni++) {
                if (BTRANS) {
                    const int row = ks * 16 + (lane & 15);
                    const int chunk = wn * 8 + ni * 2 + (lane >> 4);
                    const u32 off = row * 256 + ((chunk ^ (row & 7)) << 4);
                    ldsm4t(bh[ni][0], bh[ni][1], bh[ni][2], bh[ni][3], sBh + off);
                    if (NPROD == 3) ldsm4t(bl[ni][0], bl[ni][1], bl[ni][2], bl[ni][3], sBl + off);
                } else {
                    const int row = wn * 64 + ni * 16 + (lane & 15);
                    const u32 off = row * 128 + ((((ks << 1) | (lane >> 4)) ^ (row & 7)) << 4);
                    ldsm4(bh[ni][0], bh[ni][1], bh[ni][2], bh[ni][3], sBh + off);
                    if (NPROD == 3) ldsm4(bl[ni][0], bl[ni][1], bl[ni][2], bl[ni][3], sBl + off);
                }
            }
            const int p0 = BTRANS ? 1 : 2;   // k-hi fragment index
            const int q0 = BTRANS ? 2 : 1;   // n+8 fragment base
#pragma unroll
            for (int mi = 0; mi < 2; mi++)
#pragma unroll
                for (int ni = 0; ni < 4; ni++) {
                    mma16816(acc[mi][2 * ni + 0], ah[mi], bh[ni][0], bh[ni][p0]);
                    mma16816(acc[mi][2 * ni + 1], ah[mi], bh[ni][q0], bh[ni][3]);
                    mma16816(acc[mi][2 * ni + 0], al[mi], bh[ni][0], bh[ni][p0]);
                    mma16816(acc[mi][2 * ni + 1], al[mi], bh[ni][q0], bh[ni][3]);
                    if (NPROD == 3) {
                        mma16816(acc[mi][2 * ni + 0], ah[mi], bl[ni][0], bl[ni][p0]);
                        mma16816(acc[mi][2 * ni + 1], ah[mi], bl[ni][q0], bl[ni][3]);
                    }
                }
        }
        __syncthreads();
    }

    // epilogue
    const int mwarp = m0 + wm * 32;
    const int nwarp = n0 + wn * 64;
#pragma unroll
    for (int mi = 0; mi < 2; mi++) {
        const int r0 = mwarp + mi * 16 + (lane >> 2);
        float br0 = 0.f, br1 = 0.f;
        if (BIASROW) { br0 = bias[z * biasZ + r0]; br1 = bias[z * biasZ + r0 + 8]; }
#pragma unroll
        for (int nj = 0; nj < 8; nj++) {
            const int col = nwarp + nj * 8 + (lane & 3) * 2;
            const float* d = acc[mi][nj];
            float v00 = d[0] * scale + br0;
            float v01 = d[1] * scale + br0;
            float v10 = d[2] * scale + br1;
            float v11 = d[3] * scale + br1;
            const size_t i0 = (size_t)z * sC + (size_t)r0 * ldc + col;
            const size_t i1 = i0 + (size_t)8 * ldc;
            if (SPLIT) {
                u32 h, l;
                split2h(v00, v01, h, l);
                *(u32*)(Ch + i0) = h; *(u32*)(Cl + i0) = l;
                split2h(v10, v11, h, l);
                *(u32*)(Ch + i1) = h; *(u32*)(Cl + i1) = l;
            } else {
                *(float2*)(C + i0) = make_float2(v00, v01);
                *(float2*)(C + i1) = make_float2(v10, v11);
            }
        }
    }
}

// ---------------- elementwise kernels ----------------
__global__ void xsplit_sum(const float* __restrict__ x, half* __restrict__ xh,
                           half* __restrict__ xl, float* __restrict__ sx)
{
    const int r = blockIdx.x, tid = threadIdx.x;
    const float4* in = (const float4*)(x + (size_t)r * TT);
    uint2* oh = (uint2*)(xh + (size_t)r * TT);
    uint2* ol = (uint2*)(xl + (size_t)r * TT);
    float sum = 0.f;
#pragma unroll
    for (int i = 0; i < 4; i++) {
        const int idx = tid + i * 256;
        float4 v = in[idx];
        sum += v.x + v.y + v.z + v.w;
        uint2 h, l;
        split2h(v.x, v.y, h.x, l.x);
        split2h(v.z, v.w, h.y, l.y);
        oh[idx] = h;
        ol[idx] = l;
    }
#pragma unroll
    for (int o = 16; o > 0; o >>= 1) sum += __shfl_xor_sync(~0u, sum, o);
    __shared__ float red[8];
    if ((tid & 31) == 0) red[tid >> 5] = sum;
    __syncthreads();
    if (tid == 0) {
        float t = 0.f;
#pragma unroll
        for (int i = 0; i < 8; i++) t += red[i];
        sx[r] = t;
    }
}

// split all 3 weight matrices: grid.z selects which
__global__ void esplit3(const float* __restrict__ w0, const float* __restrict__ w1,
                        const float* __restrict__ w2, half* __restrict__ oh0,
                        half* __restrict__ ol0, half* __restrict__ oh1,
                        half* __restrict__ ol1, half* __restrict__ oh2,
                        half* __restrict__ ol2)
{
    const int which = blockIdx.y;
    const float* in = which == 0 ? w0 : (which == 1 ? w1 : w2);
    half* oh = which == 0 ? oh0 : (which == 1 ? oh1 : oh2);
    half* ol = which == 0 ? ol0 : (which == 1 ? ol1 : ol2);
    size_t i = ((size_t)blockIdx.x * blockDim.x + threadIdx.x) * 4;
    float4 v = *(const float4*)(in + i);
    uint2 h, l;
    split2h(v.x, v.y, h.x, l.x);
    split2h(v.z, v.w, h.y, l.y);
    *(uint2*)(oh + i) = h;
    *(uint2*)(ol + i) = l;
}

// sum KSPL_G partials over upper-tri tiles -> G f16 hi/lo, with mirror.
__global__ void gcombine_sym(const float* __restrict__ part, half* __restrict__ gh,
                             half* __restrict__ gl)
{
    __shared__ float t[32][33];
    const int ti = c_ti[blockIdx.y], tj = c_tj[blockIdx.y];
    const int sxo = (blockIdx.x & 3) * 32, syo = (blockIdx.x >> 2) * 32;
    const int b = blockIdx.z;
    const int r0 = ti * 128 + syo, c0 = tj * 128 + sxo;
    const int tx = threadIdx.x, ty = threadIdx.y;
    const float* pz = part + (size_t)b * KSPL_G * CCSQ;
    half* ghb = gh + (size_t)b * CCSQ;
    half* glb = gl + (size_t)b * CCSQ;
#pragma unroll
    for (int p = 0; p < 4; p++) {
        const int r = r0 + ty + p * 8;
        const size_t w = (size_t)r * CC + c0 + tx;
        float s = pz[w] + pz[w + CCSQ] + pz[w + 2 * CCSQ] + pz[w + 3 * CCSQ];
        t[ty + p * 8][tx] = s;
        __half h = __float2half_rn(s);
        ghb[w] = h;
        glb[w] = __float2half_rn(s - __half2float(h));
    }
    if (ti != tj) {
        __syncthreads();
#pragma unroll
        for (int p = 0; p < 4; p++) {
            float s = t[tx][ty + p * 8];
            const size_t w = (size_t)(c0 + ty + p * 8) * CC + r0 + tx;
            __half h = __float2half_rn(s);
            ghb[w] = h;
            glb[w] = __float2half_rn(s - __half2float(h));
        }
    }
}

// w1 = Wq*sx, w2 = Wk*sx per batch
__global__ void matvec_w(const float* __restrict__ Wq, const float* __restrict__ Wk,
                         const float* __restrict__ sx, float* __restrict__ w1,
                         float* __restrict__ w2)
{
    const int w = threadIdx.x >> 5, lane = threadIdx.x & 31;
    const int c = blockIdx.x * 8 + w, b = blockIdx.z;
    const float* W = blockIdx.y ? Wk : Wq;
    float* outp = blockIdx.y ? w2 : w1;
    const float4* Wr = (const float4*)(W + (size_t)c * CC);
    const float4* sv = (const float4*)(sx + b * CC);
    float s = 0.f;
#pragma unroll
    for (int i = 0; i < 4; i++) {
        float4 a = Wr[lane + 32 * i], xv = sv[lane + 32 * i];
        s += a.x * xv.x + a.y * xv.y + a.z * xv.z + a.w * xv.w;
    }
#pragma unroll
    for (int o = 16; o > 0; o >>= 1) s += __shfl_xor_sync(~0u, s, o);
    if (lane == 0) outp[b * CC + c] = s;
}

// softmax + rank-1 corrections + pb = attn*bv + f16 split of attn
__global__ void softmax_corr(const float* __restrict__ d, const float* __restrict__ w1,
                             const float* __restrict__ w2, const float* __restrict__ bq,
                             const float* __restrict__ bk, const float* __restrict__ bv,
                             half* __restrict__ ah, half* __restrict__ al,
                             float* __restrict__ pb)
{
    const int gw = (blockIdx.x * blockDim.x + threadIdx.x) >> 5;
    const int lane = threadIdx.x & 31;
    const int b = gw >> 9, c = gw & 511;
    const float bqc = bq[c], w1c = w1[b * CC + c];
    const float4* r = (const float4*)(d + (size_t)gw * CC);
    const float4* w2r = (const float4*)(w2 + b * CC);
    const float4* bkr = (const float4*)bk;
    const float4* bvr = (const float4*)bv;

    float4 v[4], bvv[4];
    float mx = -1e30f;
#pragma unroll
    for (int i = 0; i < 4; i++) {
        const int idx = lane + 32 * i;
        float4 dv = r[idx], w2v = w2r[idx], bkv = bkr[idx];
        bvv[i] = bvr[idx];
        v[i].x = dv.x + SCALE_F * (bqc * (w2v.x + (float)TT * bkv.x) + w1c * bkv.x);
        v[i].y = dv.y + SCALE_F * (bqc * (w2v.y + (float)TT * bkv.y) + w1c * bkv.y);
        v[i].z = dv.z + SCALE_F * (bqc * (w2v.z + (float)TT * bkv.z) + w1c * bkv.z);
        v[i].w = dv.w + SCALE_F * (bqc * (w2v.w + (float)TT * bkv.w) + w1c * bkv.w);
        mx = fmaxf(mx, fmaxf(fmaxf(v[i].x, v[i].y), fmaxf(v[i].z, v[i].w)));
    }
#pragma unroll
    for (int o = 16; o > 0; o >>= 1) mx = fmaxf(mx, __shfl_xor_sync(~0u, mx, o));
    float s = 0.f;
#pragma unroll
    for (int i = 0; i < 4; i++) {
        v[i].x = expf(v[i].x - mx); v[i].y = expf(v[i].y - mx);
        v[i].z = expf(v[i].z - mx); v[i].w = expf(v[i].w - mx);
        s += v[i].x + v[i].y + v[i].z + v[i].w;
    }
#pragma unroll
    for (int o = 16; o > 0; o >>= 1) s += __shfl_xor_sync(~0u, s, o);
    const float inv = 1.0f / s;
    float dotbv = 0.f;
#pragma unroll
    for (int i = 0; i < 4; i++) {
        v[i].x *= inv; v[i].y *= inv; v[i].z *= inv; v[i].w *= inv;
        dotbv += v[i].x * bvv[i].x + v[i].y * bvv[i].y + v[i].z * bvv[i].z + v[i].w * bvv[i].w;
        uint2 h, l;
        split2h(v[i].x, v[i].y, h.x, l.x);
        split2h(v[i].z, v[i].w, h.y, l.y);
        size_t o = (size_t)gw * CC + 4 * (lane + 32 * i);
        *(uint2*)(ah + o) = h;
        *(uint2*)(al + o) = l;
    }
#pragma unroll
    for (int o = 16; o > 0; o >>= 1) dotbv += __shfl_xor_sync(~0u, dotbv, o);
    if (lane == 0) pb[gw] = dotbv;
}

// ---------------- launch ----------------
extern "C" void kernel_launch(void* const* d_in, const int* in_sizes, int n_in,
                              void* d_out, int out_size)
{
    (void)in_sizes; (void)n_in; (void)out_size;
    const float* x  = (const float*)d_in[0];
    const float* Wq = (const float*)d_in[1];
    const float* bq = (const float*)d_in[2];
    const float* Wk = (const float*)d_in[3];
    const float* bk = (const float*)d_in[4];
    const float* Wv = (const float*)d_in[5];
    const float* bv = (const float*)d_in[6];
    float* out = (float*)d_out;

    half *xh, *xl, *wqh, *wql, *wkh, *wkl, *wvh, *wvl;
    half *Gh, *Gl, *t2h, *t2l, *aH, *aL, *Ph, *Pl;
    float *part, *dots, *sx, *w1, *w2, *pb;
    cudaGetSymbolAddress((void**)&xh, g_x_h);
    cudaGetSymbolAddress((void**)&xl, g_x_l);
    cudaGetSymbolAddress((void**)&wqh, g_wq_h);
    cudaGetSymbolAddress((void**)&wql, g_wq_l);
    cudaGetSymbolAddress((void**)&wkh, g_wk_h);
    cudaGetSymbolAddress((void**)&wkl, g_wk_l);
    cudaGetSymbolAddress((void**)&wvh, g_wv_h);
    cudaGetSymbolAddress((void**)&wvl, g_wv_l);
    cudaGetSymbolAddress((void**)&part, g_part);
    cudaGetSymbolAddress((void**)&Gh, g_G_h);
    cudaGetSymbolAddress((void**)&Gl, g_G_l);
    cudaGetSymbolAddress((void**)&t2h, g_t2_h);
    cudaGetSymbolAddress((void**)&t2l, g_t2_l);
    cudaGetSymbolAddress((void**)&dots, g_dots);
    cudaGetSymbolAddress((void**)&aH, g_a_h);
    cudaGetSymbolAddress((void**)&aL, g_a_l);
    cudaGetSymbolAddress((void**)&Ph, g_P_h);
    cudaGetSymbolAddress((void**)&Pl, g_P_l);
    cudaGetSymbolAddress((void**)&sx, g_sx);
    cudaGetSymbolAddress((void**)&w1, g_w1);
    cudaGetSymbolAddress((void**)&w2, g_w2);
    cudaGetSymbolAddress((void**)&pb, g_pb);

    const size_t CT = (size_t)CC * TT;
    const int SMEMSZ = 2 * 65536 + 1024;

    cudaFuncSetAttribute(gemm_mma<false, false, KSPL_G, true, false, 3>, cudaFuncAttributeMaxDynamicSharedMemorySize, SMEMSZ);
    cudaFuncSetAttribute(gemm_mma<false, true, 1, false, false, 3>, cudaFuncAttributeMaxDynamicSharedMemorySize, SMEMSZ);
    cudaFuncSetAttribute(gemm_mma<false, false, 1, false, false, 3>, cudaFuncAttributeMaxDynamicSharedMemorySize, SMEMSZ);
    cudaFuncSetAttribute(gemm_mma<false, true, 1, false, true, 2>, cudaFuncAttributeMaxDynamicSharedMemorySize, SMEMSZ);
    cudaFuncSetAttribute(gemm_mma<true, false, 1, false, true, 2>, cudaFuncAttributeMaxDynamicSharedMemorySize, SMEMSZ);

    // prep
    xsplit_sum<<<BB * CC, 256>>>(x, xh, xl, sx);
    esplit3<<<dim3(CCSQ / 1024, 3), 256>>>(Wq, Wk, Wv, wqh, wql, wkh, wkl, wvh, wvl);
    matvec_w<<<dim3(CC / 8, 2, BB), 256>>>(Wq, Wk, sx, w1, w2);

    // G = x x^T : upper-triangle tiles, split-K x4 partials (full 3-product)
    gemm_mma<false, false, KSPL_G, true, false, 3><<<dim3(10, 1, BB * KSPL_G), 256, SMEMSZ>>>(
        xh, xl, CT, TT, xh, xl, CT, TT, part, nullptr, nullptr,
        CCSQ, CC, nullptr, 0, 1.0f, TT / KSPL_G);
    gcombine_sym<<<dim3(16, 10, BB), dim3(32, 8)>>>(part, Gh, Gl);

    // t2 = Wq * G (3-product; precision critical)
    gemm_mma<false, true, 1, false, false, 3><<<dim3(4, 4, BB), 256, SMEMSZ>>>(
        wqh, wql, 0, CC, Gh, Gl, CCSQ, CC, nullptr, t2h, t2l,
        CCSQ, CC, nullptr, 0, 1.0f, CC);
    // dots = SCALE * t2 * Wk^T (3-product)
    gemm_mma<false, false, 1, false, false, 3><<<dim3(4, 4, BB), 256, SMEMSZ>>>(
        t2h, t2l, CCSQ, CC, wkh, wkl, 0, CC, dots, nullptr, nullptr,
        CCSQ, CC, nullptr, 0, SCALE_F, CC);
    // softmax + corrections + pb + attn split
    softmax_corr<<<BB * CC / 4, 128>>>(dots, w1, w2, bq, bk, bv, aH, aL, pb);
    // P = attn * Wv  (2-product: post-softmax linear path)
    gemm_mma<false, true, 1, false, true, 2><<<dim3(4, 4, BB), 256, SMEMSZ>>>(
        aH, aL, CCSQ, CC, wvh, wvh, 0, CC, nullptr, Ph, Pl,
        CCSQ, CC, nullptr, 0, 1.0f, CC);
    // out = P * x + pb  (2-product)
    gemm_mma<true, false, 1, false, true, 2><<<dim3(TT / 128, CC / 128, BB), 256, SMEMSZ>>>(
        Ph, Pl, CCSQ, CC, xh, xh, CT, TT, out, nullptr, nullptr,
        CT, TT, pb, CC, 1.0f, CC);
}